// round 9
// baseline (speedup 1.0000x reference)
#include <cuda_runtime.h>
#include <cuda_bf16.h>
#include <cstdint>

// ---------------- constants ----------------
#define NB      8
#define CI      256
#define HW      1600
#define DM      128
#define NHEAD   8
#define DH      16
#define NROWS   (NB*HW)        // 12800
#define NCLOUD  32768

// ---------------- device scratch ----------------
__device__ float g_tok [NROWS*DM];     // l2-normalized image tokens
__device__ float g_attn[NROWS*DM];     // attention output
__device__ float g_m0  [NB*NHEAD*DH];  // per (b,h) sum of v over keys
__device__ float g_imgacc[NB*CI];
__device__ float g_seg  [NB*DM];
__device__ float g_cnt  [NB];

typedef unsigned long long u64;

// ---------------- packed f32x2 helpers ----------------
__device__ __forceinline__ u64 fma2(u64 a, u64 b, u64 c){
  u64 d; asm("fma.rn.f32x2 %0, %1, %2, %3;" : "=l"(d) : "l"(a), "l"(b), "l"(c)); return d;
}
__device__ __forceinline__ u64 mul2(u64 a, u64 b){
  u64 d; asm("mul.rn.f32x2 %0, %1, %2;" : "=l"(d) : "l"(a), "l"(b)); return d;
}
__device__ __forceinline__ u64 add2(u64 a, u64 b){
  u64 d; asm("add.rn.f32x2 %0, %1, %2;" : "=l"(d) : "l"(a), "l"(b)); return d;
}
__device__ __forceinline__ u64 pack2(float x, float y){
  u64 d; asm("mov.b64 %0, {%1, %2};" : "=l"(d) : "f"(x), "f"(y)); return d;
}
__device__ __forceinline__ float2 unpack2(u64 u){
  float2 f; asm("mov.b64 {%0, %1}, %2;" : "=f"(f.x), "=f"(f.y) : "l"(u)); return f;
}

// bf16x2 pack: lower = f.x, upper = f.y
__device__ __forceinline__ uint32_t cvt_bf16x2(u64 p){
  float2 f = unpack2(p);
  uint32_t r;
  asm("cvt.rn.bf16x2.f32 %0, %1, %2;" : "=r"(r) : "f"(f.y), "f"(f.x));
  return r;
}
__device__ __forceinline__ uint32_t cvt_bf16x2_ff(float lo, float hi){
  uint32_t r;
  asm("cvt.rn.bf16x2.f32 %0, %1, %2;" : "=r"(r) : "f"(hi), "f"(lo));
  return r;
}
__device__ __forceinline__ uint32_t packbf(__nv_bfloat16 a, __nv_bfloat16 b){
  __nv_bfloat162 t(a, b);
  return *reinterpret_cast<uint32_t*>(&t);
}

// ---------------- mma / ldmatrix helpers ----------------
__device__ __forceinline__ void mma_bf16(float* c, const uint32_t* a, uint32_t b0, uint32_t b1){
  asm volatile("mma.sync.aligned.m16n8k16.row.col.f32.bf16.bf16.f32 "
      "{%0,%1,%2,%3}, {%4,%5,%6,%7}, {%8,%9}, {%0,%1,%2,%3};"
      : "+f"(c[0]), "+f"(c[1]), "+f"(c[2]), "+f"(c[3])
      : "r"(a[0]), "r"(a[1]), "r"(a[2]), "r"(a[3]), "r"(b0), "r"(b1));
}
__device__ __forceinline__ void ldsm4(uint32_t addr, uint32_t* r){
  asm volatile("ldmatrix.sync.aligned.m8n8.x4.shared.b16 {%0,%1,%2,%3}, [%4];"
      : "=r"(r[0]), "=r"(r[1]), "=r"(r[2]), "=r"(r[3]) : "r"(addr));
}
__device__ __forceinline__ void ldsm4t(uint32_t addr, uint32_t* r){
  asm volatile("ldmatrix.sync.aligned.m8n8.x4.trans.shared.b16 {%0,%1,%2,%3}, [%4];"
      : "=r"(r[0]), "=r"(r[1]), "=r"(r[2]), "=r"(r[3]) : "r"(addr));
}
__device__ __forceinline__ void sts64(uint32_t addr, uint32_t r0, uint32_t r1){
  asm volatile("st.shared.v2.b32 [%0], {%1,%2};" :: "r"(addr), "r"(r0), "r"(r1));
}

// ---------------- K0: zero accumulators ----------------
__global__ void zero_kernel(){
  int i = blockIdx.x*256 + threadIdx.x;
  if (i < NB*CI) g_imgacc[i] = 0.f;
  if (i < NB*DM) g_seg[i]    = 0.f;
  if (i < NB)    g_cnt[i]    = 0.f;
}

// ---------------- K1: x = einsum(bchw,cd)+b1, rowwise l2norm -> g_tok --------
__global__ __launch_bounds__(256) void gemm1_kernel(const float* __restrict__ img,
                                                    const float* __restrict__ W1,
                                                    const float* __restrict__ b1){
  __shared__ float As[32][64];
  __shared__ float Ws[32][128];
  int tile = blockIdx.x;
  int b = tile / 25;
  int pbase = (tile % 25) * 64;
  const float* Ab = img + b*CI*HW + pbase;
  int tid = threadIdx.x;
  int rgrp = tid >> 5, lane = tid & 31;
  float acc[8][4];
  #pragma unroll
  for (int i=0;i<8;i++){ acc[i][0]=0.f; acc[i][1]=0.f; acc[i][2]=0.f; acc[i][3]=0.f; }

  for (int kt=0; kt<8; kt++){
    __syncthreads();
    #pragma unroll
    for (int it=0; it<8; it++){
      int idx = tid + it*256;
      int r = idx & 63, k = idx >> 6;
      As[k][r] = Ab[(kt*32+k)*HW + r];
    }
    #pragma unroll
    for (int it=0; it<4; it++){
      int idx = tid + it*256;
      int c4 = idx & 31, k = idx >> 5;
      *(float4*)&Ws[k][c4*4] = *(const float4*)(W1 + (kt*32+k)*DM + c4*4);
    }
    __syncthreads();
    #pragma unroll 8
    for (int k=0;k<32;k++){
      float4 w  = *(float4*)&Ws[k][lane*4];
      float4 a0 = *(float4*)&As[k][rgrp*8];
      float4 a1 = *(float4*)&As[k][rgrp*8+4];
      float a[8] = {a0.x,a0.y,a0.z,a0.w,a1.x,a1.y,a1.z,a1.w};
      #pragma unroll
      for (int i=0;i<8;i++){
        acc[i][0] = fmaf(a[i], w.x, acc[i][0]);
        acc[i][1] = fmaf(a[i], w.y, acc[i][1]);
        acc[i][2] = fmaf(a[i], w.z, acc[i][2]);
        acc[i][3] = fmaf(a[i], w.w, acc[i][3]);
      }
    }
  }
  float4 bb = *(const float4*)(b1 + lane*4);
  int Rbase = tile*64 + rgrp*8;
  #pragma unroll
  for (int i=0;i<8;i++){
    float x0 = acc[i][0]+bb.x, x1 = acc[i][1]+bb.y, x2 = acc[i][2]+bb.z, x3 = acc[i][3]+bb.w;
    float sq = x0*x0 + x1*x1 + x2*x2 + x3*x3;
    #pragma unroll
    for (int off=16; off; off>>=1) sq += __shfl_xor_sync(0xffffffffu, sq, off);
    float inv = 1.0f / fmaxf(sqrtf(sq), 1e-12f);
    *(float4*)(g_tok + (Rbase+i)*DM + lane*4) = make_float4(x0*inv, x1*inv, x2*inv, x3*inv);
  }
}

// ---------------- K2: M0[b,h,d] = sum over keys of v ----------------
__global__ __launch_bounds__(128) void m0_kernel(){
  int bh = blockIdx.x;
  const float* base = g_tok + (bh>>3)*HW*DM + (bh&7)*DH;
  __shared__ float red[128];
  int tid = threadIdx.x;
  int d = tid & 15, seg = tid >> 4;
  float s = 0.f;
  for (int t = seg; t < HW; t += 8) s += base[t*DM + d];
  red[tid] = s;
  __syncthreads();
  if (tid < 16){
    float a = 0.f;
    #pragma unroll
    for (int i=0;i<8;i++) a += red[tid + i*16];
    g_m0[bh*16 + tid] = a;
  }
}

// ---------------- K3: attention, q-exact/k-bf16 scores, 8 warps/CTA ----------
// S = qh*kh + ql*kh (q split exact, k bf16). u = expm1(S) deg-4.
// P(bf16, regs) -> PV mma. O = M0 + U*V, l = 1600 + sum u.
// smem buffer: plane A (dims 0-7) @0, plane B (dims 8-15) @1024; 2 buffers.
__global__ __launch_bounds__(256) void attn_bf16_kernel(){
  __shared__ __align__(1024) unsigned char sbuf[2][2048];
  int b = blockIdx.z, h = blockIdx.y;
  int tid = threadIdx.x, w = tid >> 5, lane = tid & 31;
  int gid = lane >> 2, tig = lane & 3;
  const float* base = g_tok + b*HW*DM + h*DH;
  int qb0 = blockIdx.x*128 + w*16;
  bool wstore = (qb0 < HW);
  int qbase = wstore ? qb0 : (HW - 16);

  // ---- Q fragments, scaled by 0.25 (exact), split hi/lo ----
  uint32_t qh[4], ql[4];
  #pragma unroll
  for (int i=0;i<4;i++){
    int row = qbase + gid + (i & 1)*8;
    int col = 2*tig + (i >> 1)*8;
    float2 v = *(const float2*)(base + row*DM + col);
    float x0 = v.x*0.25f, x1 = v.y*0.25f;
    __nv_bfloat16 h0 = __float2bfloat16_rn(x0);
    __nv_bfloat16 h1 = __float2bfloat16_rn(x1);
    float r0 = x0 - __bfloat162float(h0);
    float r1 = x1 - __bfloat162float(h1);
    qh[i] = packbf(h0, h1);
    ql[i] = packbf(__float2bfloat16_rn(r0), __float2bfloat16_rn(r1));
  }

  float oa0[4] = {0.f,0.f,0.f,0.f};
  float oa1[4] = {0.f,0.f,0.f,0.f};
  u64 lA01 = 0ULL, lA23 = 0ULL, lB01 = 0ULL, lB23 = 0ULL;

  const u64 C24 = pack2(4.1666667e-2f, 4.1666667e-2f);
  const u64 C6  = pack2(1.6666667e-1f, 1.6666667e-1f);
  const u64 CH  = pack2(0.5f, 0.5f);
  const u64 C1  = pack2(1.0f, 1.0f);

  // ---- ldmatrix per-lane base addresses ----
  uint32_t sb0 = (uint32_t)__cvta_generic_to_shared(&sbuf[0][0]);
  int r7 = lane & 7;
  uint32_t aScore = sb0 + (uint32_t)((r7 + ((lane >> 4) & 1)*8)*16 + ((lane >> 3) & 1)*1024);
  uint32_t aPV    = sb0 + (uint32_t)((r7 + ((lane >> 3) & 1)*8)*16 + ((lane >> 4) & 1)*1024);

  // ---- tile store addressing: 256 threads, 1 float4 each ----
  int key = tid >> 2, quarter = tid & 3;
  const float* gsrc = base + key*DM + quarter*4;
  uint32_t dstK = sb0 + (uint32_t)((quarter >> 1)*1024 + key*16 + (quarter & 1)*8);

  // prologue: tile 0 -> buffer 0
  {
    float4 v = *(const float4*)(gsrc);
    sts64(dstK, cvt_bf16x2_ff(v.x, v.y), cvt_bf16x2_ff(v.z, v.w));
  }
  __syncthreads();

  for (int kb=0; kb<25; kb++){
    float4 nv;
    if (kb < 24) nv = *(const float4*)(gsrc + (kb+1)*64*DM);
    uint32_t bufoff = (uint32_t)((kb & 1)*2048);
    uint32_t aS = aScore + bufoff;
    uint32_t aP = aPV + bufoff;

    #pragma unroll
    for (int ck=0; ck<4; ck++){
      uint32_t off = (uint32_t)(ck*256);
      uint32_t kh[4], vv[4];
      ldsm4 (aS + off, kh);
      ldsm4t(aP + off, vv);

      float cA[4] = {0.f,0.f,0.f,0.f};
      float cB[4] = {0.f,0.f,0.f,0.f};
      mma_bf16(cA, qh, kh[0], kh[1]);
      mma_bf16(cA, ql, kh[0], kh[1]);
      mma_bf16(cB, qh, kh[2], kh[3]);
      mma_bf16(cB, ql, kh[2], kh[3]);

      // u = expm1(t), deg-4, packed pairs
      u64 tA01 = pack2(cA[0], cA[1]);
      u64 tA23 = pack2(cA[2], cA[3]);
      u64 tB01 = pack2(cB[0], cB[1]);
      u64 tB23 = pack2(cB[2], cB[3]);
      u64 wA01 = fma2(tA01, C24, C6);
      u64 wA23 = fma2(tA23, C24, C6);
      u64 wB01 = fma2(tB01, C24, C6);
      u64 wB23 = fma2(tB23, C24, C6);
      wA01 = fma2(tA01, wA01, CH);  wA23 = fma2(tA23, wA23, CH);
      wB01 = fma2(tB01, wB01, CH);  wB23 = fma2(tB23, wB23, CH);
      wA01 = fma2(tA01, wA01, C1);  wA23 = fma2(tA23, wA23, C1);
      wB01 = fma2(tB01, wB01, C1);  wB23 = fma2(tB23, wB23, C1);
      u64 uA01 = mul2(tA01, wA01);
      u64 uA23 = mul2(tA23, wA23);
      u64 uB01 = mul2(tB01, wB01);
      u64 uB23 = mul2(tB23, wB23);
      lA01 = add2(lA01, uA01);
      lA23 = add2(lA23, uA23);
      lB01 = add2(lB01, uB01);
      lB23 = add2(lB23, uB23);

      // P -> bf16 A fragment (register chaining)
      uint32_t pa[4];
      pa[0] = cvt_bf16x2(uA01);
      pa[1] = cvt_bf16x2(uA23);
      pa[2] = cvt_bf16x2(uB01);
      pa[3] = cvt_bf16x2(uB23);

      mma_bf16(oa0, pa, vv[0], vv[1]);   // dims 0-7
      mma_bf16(oa1, pa, vv[2], vv[3]);   // dims 8-15
    }

    if (kb < 24){
      uint32_t d = dstK + (uint32_t)(((kb+1) & 1)*2048);
      sts64(d, cvt_bf16x2_ff(nv.x, nv.y), cvt_bf16x2_ff(nv.z, nv.w));
    }
    __syncthreads();
  }

  // ---- epilogue ----
  float2 fA01 = unpack2(lA01), fA23 = unpack2(lA23);
  float2 fB01 = unpack2(lB01), fB23 = unpack2(lB23);
  float lr0 = fA01.x + fA01.y + fB01.x + fB01.y;
  float lr8 = fA23.x + fA23.y + fB23.x + fB23.y;
  lr0 += __shfl_xor_sync(0xffffffffu, lr0, 1);
  lr0 += __shfl_xor_sync(0xffffffffu, lr0, 2);
  lr8 += __shfl_xor_sync(0xffffffffu, lr8, 1);
  lr8 += __shfl_xor_sync(0xffffffffu, lr8, 2);
  float inv0 = 1.0f / (1600.0f + lr0);
  float inv8 = 1.0f / (1600.0f + lr8);

  if (wstore){
    const float* m0p = g_m0 + (b*NHEAD + h)*16;
    float* outb = g_attn + (b*HW + qbase)*DM + h*DH;
    float* oas[2] = {oa0, oa1};
    #pragma unroll
    for (int nt=0; nt<2; nt++){
      int d0 = nt*8 + 2*tig;
      float m0a = m0p[d0], m0b = m0p[d0+1];
      outb[(gid  )*DM + d0    ] = (oas[nt][0] + m0a) * inv0;
      outb[(gid  )*DM + d0 + 1] = (oas[nt][1] + m0b) * inv0;
      outb[(gid+8)*DM + d0    ] = (oas[nt][2] + m0a) * inv8;
      outb[(gid+8)*DM + d0 + 1] = (oas[nt][3] + m0b) * inv8;
    }
  }
}

// ---------------- K4: img_out = attn @ W2 + b2, transposed write + GeM partials
__global__ __launch_bounds__(256) void gemm2_kernel(const float* __restrict__ W2,
                                                    const float* __restrict__ b2,
                                                    float* __restrict__ img_out){
  __shared__ float As[64][33];
  __shared__ float Ws[32][128];
  __shared__ float colsum[128];
  int tile = blockIdx.x, ct = blockIdx.y;
  int b = tile / 25, pbase = (tile % 25) * 64;
  int tid = threadIdx.x, rgrp = tid >> 5, lane = tid & 31;
  if (tid < 128) colsum[tid] = 0.f;
  float acc[8][4];
  #pragma unroll
  for (int i=0;i<8;i++){ acc[i][0]=0.f; acc[i][1]=0.f; acc[i][2]=0.f; acc[i][3]=0.f; }

  for (int kt=0; kt<4; kt++){
    __syncthreads();
    #pragma unroll
    for (int it=0; it<2; it++){
      int idx = tid + it*256;
      int k4 = idx & 7, r = idx >> 3;
      float4 v = *(const float4*)(g_attn + (tile*64 + r)*DM + kt*32 + k4*4);
      As[r][k4*4+0]=v.x; As[r][k4*4+1]=v.y; As[r][k4*4+2]=v.z; As[r][k4*4+3]=v.w;
    }
    #pragma unroll
    for (int it=0; it<4; it++){
      int idx = tid + it*256;
      int c4 = idx & 31, k = idx >> 5;
      *(float4*)&Ws[k][c4*4] = *(const float4*)(W2 + (kt*32+k)*CI + ct*128 + c4*4);
    }
    __syncthreads();
    #pragma unroll 8
    for (int k=0;k<32;k++){
      float4 w = *(float4*)&Ws[k][lane*4];
      #pragma unroll
      for (int i=0;i<8;i++){
        float a = As[rgrp*8+i][k];
        acc[i][0] = fmaf(a, w.x, acc[i][0]);
        acc[i][1] = fmaf(a, w.y, acc[i][1]);
        acc[i][2] = fmaf(a, w.z, acc[i][2]);
        acc[i][3] = fmaf(a, w.w, acc[i][3]);
      }
    }
  }
  float4 bb = *(const float4*)(b2 + ct*128 + lane*4);
  float bv[4] = {bb.x, bb.y, bb.z, bb.w};
  #pragma unroll
  for (int j=0;j<4;j++){
    float part = 0.f; float vs[8];
    #pragma unroll
    for (int i=0;i<8;i++){
      float v = acc[i][j] + bv[j];
      vs[i] = v;
      float c = fmaxf(v, 1e-6f);
      part = fmaf(c*c, c, part);
    }
    atomicAdd(&colsum[lane*4+j], part);
    int cg = ct*128 + lane*4 + j;
    float* dst = img_out + b*CI*HW + cg*HW + pbase + rgrp*8;
    *(float4*)(dst)     = make_float4(vs[0],vs[1],vs[2],vs[3]);
    *(float4*)(dst + 4) = make_float4(vs[4],vs[5],vs[6],vs[7]);
  }
  __syncthreads();
  if (tid < 128) atomicAdd(&g_imgacc[b*CI + ct*128 + tid], colsum[tid]);
}

// ---------------- K7: cloud l2norm + segmented clamp^3 sum -------------------
// 512 blocks, 8 rows per warp (latency-bound fix: >3 CTAs/SM)
__global__ __launch_bounds__(256) void cloud_kernel(const float* __restrict__ cf,
                                                    const int* __restrict__ bids,
                                                    float* __restrict__ cloud_out){
  __shared__ float sseg[NB*DM];
  __shared__ float scnt[NB];
  int tid = threadIdx.x;
  for (int i=tid; i<NB*DM; i+=256) sseg[i] = 0.f;
  if (tid < NB) scnt[tid] = 0.f;
  __syncthreads();
  int w = tid >> 5, lane = tid & 31;
  int rbase = blockIdx.x*64 + w*8;
  #pragma unroll
  for (int i=0;i<8;i++){
    int row = rbase + i;
    int bid = bids[row];
    float4 v = *(const float4*)(cf + row*DM + lane*4);
    float sq = v.x*v.x + v.y*v.y + v.z*v.z + v.w*v.w;
    #pragma unroll
    for (int off=16; off; off>>=1) sq += __shfl_xor_sync(0xffffffffu, sq, off);
    float inv = 1.0f / fmaxf(sqrtf(sq), 1e-12f);
    float x0=v.x*inv, x1=v.y*inv, x2=v.z*inv, x3=v.w*inv;
    *(float4*)(cloud_out + row*DM + lane*4) = make_float4(x0,x1,x2,x3);
    float c0=fmaxf(x0,1e-6f), c1=fmaxf(x1,1e-6f), c2=fmaxf(x2,1e-6f), c3=fmaxf(x3,1e-6f);
    float* sp = sseg + bid*DM + lane*4;
    atomicAdd(sp+0, c0*c0*c0);
    atomicAdd(sp+1, c1*c1*c1);
    atomicAdd(sp+2, c2*c2*c2);
    atomicAdd(sp+3, c3*c3*c3);
    if (lane == 0) atomicAdd(&scnt[bid], 1.0f);
  }
  __syncthreads();
  for (int i=tid; i<NB*DM; i+=256) atomicAdd(&g_seg[i], sseg[i]);
  if (tid < NB) atomicAdd(&g_cnt[tid], scnt[tid]);
}

// ---------------- K8: finalize GeM outputs ----------------
__global__ void finalize_kernel(float* __restrict__ image_gem, float* __restrict__ cloud_gem){
  int i = blockIdx.x*256 + threadIdx.x;
  if (i < NB*CI) image_gem[i] = cbrtf(g_imgacc[i] * (1.0f/1600.0f));
  if (i < NB*DM) cloud_gem[i] = cbrtf(g_seg[i] / fmaxf(g_cnt[i>>7], 1.0f));
}

// ---------------- launch ----------------
extern "C" void kernel_launch(void* const* d_in, const int* in_sizes, int n_in,
                              void* d_out, int out_size){
  const float* img  = (const float*)d_in[0];
  const float* cf   = (const float*)d_in[1];
  const int*   bids = (const int*)  d_in[2];
  const float* W1   = (const float*)d_in[3];
  const float* b1   = (const float*)d_in[4];
  const float* W2   = (const float*)d_in[5];
  const float* b2   = (const float*)d_in[6];

  float* out       = (float*)d_out;
  float* img_out   = out;                                  // 8*256*1600
  float* cloud_out = out + (size_t)NB*CI*HW;               // 32768*128
  float* image_gem = cloud_out + (size_t)NCLOUD*DM;        // 2048
  float* cloud_gem = image_gem + NB*CI;                    // 1024

  zero_kernel<<<8, 256>>>();
  gemm1_kernel<<<200, 256>>>(img, W1, b1);
  m0_kernel<<<NB*NHEAD, 128>>>();
  attn_bf16_kernel<<<dim3(13, NHEAD, NB), 256>>>();
  gemm2_kernel<<<dim3(200, 2), 256>>>(W2, b2, img_out);
  cloud_kernel<<<512, 256>>>(cf, bids, cloud_out);
  finalize_kernel<<<8, 256>>>(image_gem, cloud_gem);
}

// round 10
// speedup vs baseline: 1.0007x; 1.0007x over previous
#include <cuda_runtime.h>
#include <cuda_bf16.h>
#include <cstdint>

// ---------------- constants ----------------
#define NB      8
#define CI      256
#define HW      1600
#define DM      128
#define NHEAD   8
#define DH      16
#define NROWS   (NB*HW)        // 12800
#define NCLOUD  32768

// ---------------- device scratch ----------------
__device__ float g_tok [NROWS*DM];     // l2-normalized image tokens
__device__ float g_attn[NROWS*DM];     // attention output
__device__ float g_m0  [NB*NHEAD*DH];  // per (b,h) sum of v over keys
__device__ float g_imgacc[NB*CI];
__device__ float g_seg  [NB*DM];
__device__ float g_cnt  [NB];

typedef unsigned long long u64;

// ---------------- packed f32x2 helpers ----------------
__device__ __forceinline__ u64 fma2(u64 a, u64 b, u64 c){
  u64 d; asm("fma.rn.f32x2 %0, %1, %2, %3;" : "=l"(d) : "l"(a), "l"(b), "l"(c)); return d;
}
__device__ __forceinline__ u64 mul2(u64 a, u64 b){
  u64 d; asm("mul.rn.f32x2 %0, %1, %2;" : "=l"(d) : "l"(a), "l"(b)); return d;
}
__device__ __forceinline__ u64 add2(u64 a, u64 b){
  u64 d; asm("add.rn.f32x2 %0, %1, %2;" : "=l"(d) : "l"(a), "l"(b)); return d;
}
__device__ __forceinline__ u64 pack2(float x, float y){
  u64 d; asm("mov.b64 %0, {%1, %2};" : "=l"(d) : "f"(x), "f"(y)); return d;
}
__device__ __forceinline__ float2 unpack2(u64 u){
  float2 f; asm("mov.b64 {%0, %1}, %2;" : "=f"(f.x), "=f"(f.y) : "l"(u)); return f;
}

// bf16x2 pack: lower = f.x, upper = f.y
__device__ __forceinline__ uint32_t cvt_bf16x2(u64 p){
  float2 f = unpack2(p);
  uint32_t r;
  asm("cvt.rn.bf16x2.f32 %0, %1, %2;" : "=r"(r) : "f"(f.y), "f"(f.x));
  return r;
}
__device__ __forceinline__ uint32_t cvt_bf16x2_ff(float lo, float hi){
  uint32_t r;
  asm("cvt.rn.bf16x2.f32 %0, %1, %2;" : "=r"(r) : "f"(hi), "f"(lo));
  return r;
}
__device__ __forceinline__ uint32_t packbf(__nv_bfloat16 a, __nv_bfloat16 b){
  __nv_bfloat162 t(a, b);
  return *reinterpret_cast<uint32_t*>(&t);
}

// ---------------- mma / ldmatrix helpers ----------------
__device__ __forceinline__ void mma_bf16(float* c, const uint32_t* a, uint32_t b0, uint32_t b1){
  asm volatile("mma.sync.aligned.m16n8k16.row.col.f32.bf16.bf16.f32 "
      "{%0,%1,%2,%3}, {%4,%5,%6,%7}, {%8,%9}, {%0,%1,%2,%3};"
      : "+f"(c[0]), "+f"(c[1]), "+f"(c[2]), "+f"(c[3])
      : "r"(a[0]), "r"(a[1]), "r"(a[2]), "r"(a[3]), "r"(b0), "r"(b1));
}
__device__ __forceinline__ void ldsm4(uint32_t addr, uint32_t* r){
  asm volatile("ldmatrix.sync.aligned.m8n8.x4.shared.b16 {%0,%1,%2,%3}, [%4];"
      : "=r"(r[0]), "=r"(r[1]), "=r"(r[2]), "=r"(r[3]) : "r"(addr));
}
__device__ __forceinline__ void ldsm4t(uint32_t addr, uint32_t* r){
  asm volatile("ldmatrix.sync.aligned.m8n8.x4.trans.shared.b16 {%0,%1,%2,%3}, [%4];"
      : "=r"(r[0]), "=r"(r[1]), "=r"(r[2]), "=r"(r[3]) : "r"(addr));
}
__device__ __forceinline__ void sts64(uint32_t addr, uint32_t r0, uint32_t r1){
  asm volatile("st.shared.v2.b32 [%0], {%1,%2};" :: "r"(addr), "r"(r0), "r"(r1));
}

// ---------------- K0: zero accumulators ----------------
__global__ void zero_kernel(){
  int i = blockIdx.x*256 + threadIdx.x;
  if (i < NB*CI) g_imgacc[i] = 0.f;
  if (i < NB*DM) g_seg[i]    = 0.f;
  if (i < NB)    g_cnt[i]    = 0.f;
}

// ---------------- K1: x = einsum(bchw,cd)+b1, rowwise l2norm -> g_tok --------
__global__ __launch_bounds__(256) void gemm1_kernel(const float* __restrict__ img,
                                                    const float* __restrict__ W1,
                                                    const float* __restrict__ b1){
  __shared__ float As[32][64];
  __shared__ float Ws[32][128];
  int tile = blockIdx.x;
  int b = tile / 25;
  int pbase = (tile % 25) * 64;
  const float* Ab = img + b*CI*HW + pbase;
  int tid = threadIdx.x;
  int rgrp = tid >> 5, lane = tid & 31;
  float acc[8][4];
  #pragma unroll
  for (int i=0;i<8;i++){ acc[i][0]=0.f; acc[i][1]=0.f; acc[i][2]=0.f; acc[i][3]=0.f; }

  for (int kt=0; kt<8; kt++){
    __syncthreads();
    #pragma unroll
    for (int it=0; it<8; it++){
      int idx = tid + it*256;
      int r = idx & 63, k = idx >> 6;
      As[k][r] = Ab[(kt*32+k)*HW + r];
    }
    #pragma unroll
    for (int it=0; it<4; it++){
      int idx = tid + it*256;
      int c4 = idx & 31, k = idx >> 5;
      *(float4*)&Ws[k][c4*4] = *(const float4*)(W1 + (kt*32+k)*DM + c4*4);
    }
    __syncthreads();
    #pragma unroll 8
    for (int k=0;k<32;k++){
      float4 w  = *(float4*)&Ws[k][lane*4];
      float4 a0 = *(float4*)&As[k][rgrp*8];
      float4 a1 = *(float4*)&As[k][rgrp*8+4];
      float a[8] = {a0.x,a0.y,a0.z,a0.w,a1.x,a1.y,a1.z,a1.w};
      #pragma unroll
      for (int i=0;i<8;i++){
        acc[i][0] = fmaf(a[i], w.x, acc[i][0]);
        acc[i][1] = fmaf(a[i], w.y, acc[i][1]);
        acc[i][2] = fmaf(a[i], w.z, acc[i][2]);
        acc[i][3] = fmaf(a[i], w.w, acc[i][3]);
      }
    }
  }
  float4 bb = *(const float4*)(b1 + lane*4);
  int Rbase = tile*64 + rgrp*8;
  #pragma unroll
  for (int i=0;i<8;i++){
    float x0 = acc[i][0]+bb.x, x1 = acc[i][1]+bb.y, x2 = acc[i][2]+bb.z, x3 = acc[i][3]+bb.w;
    float sq = x0*x0 + x1*x1 + x2*x2 + x3*x3;
    #pragma unroll
    for (int off=16; off; off>>=1) sq += __shfl_xor_sync(0xffffffffu, sq, off);
    float inv = 1.0f / fmaxf(sqrtf(sq), 1e-12f);
    *(float4*)(g_tok + (Rbase+i)*DM + lane*4) = make_float4(x0*inv, x1*inv, x2*inv, x3*inv);
  }
}

// ---------------- K2: M0[b,h,d] = sum over keys of v ----------------
__global__ __launch_bounds__(128) void m0_kernel(){
  int bh = blockIdx.x;
  const float* base = g_tok + (bh>>3)*HW*DM + (bh&7)*DH;
  __shared__ float red[128];
  int tid = threadIdx.x;
  int d = tid & 15, seg = tid >> 4;
  float s = 0.f;
  for (int t = seg; t < HW; t += 8) s += base[t*DM + d];
  red[tid] = s;
  __syncthreads();
  if (tid < 16){
    float a = 0.f;
    #pragma unroll
    for (int i=0;i<8;i++) a += red[tid + i*16];
    g_m0[bh*16 + tid] = a;
  }
}

// ---------------- K3: attention, q-exact/k-bf16 scores, 8 warps/CTA ----------
// S = qh*kh + ql*kh (q split exact, k bf16). u = expm1(S) deg-4.
// P(bf16, regs) -> PV mma. O = M0 + U*V, l = 1600 + sum u.
// smem buffer: plane A (dims 0-7) @0, plane B (dims 8-15) @1024; 2 buffers.
__global__ __launch_bounds__(256) void attn_bf16_kernel(){
  __shared__ __align__(1024) unsigned char sbuf[2][2048];
  int b = blockIdx.z, h = blockIdx.y;
  int tid = threadIdx.x, w = tid >> 5, lane = tid & 31;
  int gid = lane >> 2, tig = lane & 3;
  const float* base = g_tok + b*HW*DM + h*DH;
  int qb0 = blockIdx.x*128 + w*16;
  bool wstore = (qb0 < HW);
  int qbase = wstore ? qb0 : (HW - 16);

  // ---- Q fragments, scaled by 0.25 (exact), split hi/lo ----
  uint32_t qh[4], ql[4];
  #pragma unroll
  for (int i=0;i<4;i++){
    int row = qbase + gid + (i & 1)*8;
    int col = 2*tig + (i >> 1)*8;
    float2 v = *(const float2*)(base + row*DM + col);
    float x0 = v.x*0.25f, x1 = v.y*0.25f;
    __nv_bfloat16 h0 = __float2bfloat16_rn(x0);
    __nv_bfloat16 h1 = __float2bfloat16_rn(x1);
    float r0 = x0 - __bfloat162float(h0);
    float r1 = x1 - __bfloat162float(h1);
    qh[i] = packbf(h0, h1);
    ql[i] = packbf(__float2bfloat16_rn(r0), __float2bfloat16_rn(r1));
  }

  float oa0[4] = {0.f,0.f,0.f,0.f};
  float oa1[4] = {0.f,0.f,0.f,0.f};
  u64 lA01 = 0ULL, lA23 = 0ULL, lB01 = 0ULL, lB23 = 0ULL;

  const u64 C24 = pack2(4.1666667e-2f, 4.1666667e-2f);
  const u64 C6  = pack2(1.6666667e-1f, 1.6666667e-1f);
  const u64 CH  = pack2(0.5f, 0.5f);
  const u64 C1  = pack2(1.0f, 1.0f);

  // ---- ldmatrix per-lane base addresses ----
  uint32_t sb0 = (uint32_t)__cvta_generic_to_shared(&sbuf[0][0]);
  int r7 = lane & 7;
  uint32_t aScore = sb0 + (uint32_t)((r7 + ((lane >> 4) & 1)*8)*16 + ((lane >> 3) & 1)*1024);
  uint32_t aPV    = sb0 + (uint32_t)((r7 + ((lane >> 3) & 1)*8)*16 + ((lane >> 4) & 1)*1024);

  // ---- tile store addressing: 256 threads, 1 float4 each ----
  int key = tid >> 2, quarter = tid & 3;
  const float* gsrc = base + key*DM + quarter*4;
  uint32_t dstK = sb0 + (uint32_t)((quarter >> 1)*1024 + key*16 + (quarter & 1)*8);

  // prologue: tile 0 -> buffer 0
  {
    float4 v = *(const float4*)(gsrc);
    sts64(dstK, cvt_bf16x2_ff(v.x, v.y), cvt_bf16x2_ff(v.z, v.w));
  }
  __syncthreads();

  for (int kb=0; kb<25; kb++){
    float4 nv;
    if (kb < 24) nv = *(const float4*)(gsrc + (kb+1)*64*DM);
    uint32_t bufoff = (uint32_t)((kb & 1)*2048);
    uint32_t aS = aScore + bufoff;
    uint32_t aP = aPV + bufoff;

    #pragma unroll
    for (int ck=0; ck<4; ck++){
      uint32_t off = (uint32_t)(ck*256);
      uint32_t kh[4], vv[4];
      ldsm4 (aS + off, kh);
      ldsm4t(aP + off, vv);

      float cA[4] = {0.f,0.f,0.f,0.f};
      float cB[4] = {0.f,0.f,0.f,0.f};
      mma_bf16(cA, qh, kh[0], kh[1]);
      mma_bf16(cA, ql, kh[0], kh[1]);
      mma_bf16(cB, qh, kh[2], kh[3]);
      mma_bf16(cB, ql, kh[2], kh[3]);

      // u = expm1(t), deg-4, packed pairs
      u64 tA01 = pack2(cA[0], cA[1]);
      u64 tA23 = pack2(cA[2], cA[3]);
      u64 tB01 = pack2(cB[0], cB[1]);
      u64 tB23 = pack2(cB[2], cB[3]);
      u64 wA01 = fma2(tA01, C24, C6);
      u64 wA23 = fma2(tA23, C24, C6);
      u64 wB01 = fma2(tB01, C24, C6);
      u64 wB23 = fma2(tB23, C24, C6);
      wA01 = fma2(tA01, wA01, CH);  wA23 = fma2(tA23, wA23, CH);
      wB01 = fma2(tB01, wB01, CH);  wB23 = fma2(tB23, wB23, CH);
      wA01 = fma2(tA01, wA01, C1);  wA23 = fma2(tA23, wA23, C1);
      wB01 = fma2(tB01, wB01, C1);  wB23 = fma2(tB23, wB23, C1);
      u64 uA01 = mul2(tA01, wA01);
      u64 uA23 = mul2(tA23, wA23);
      u64 uB01 = mul2(tB01, wB01);
      u64 uB23 = mul2(tB23, wB23);
      lA01 = add2(lA01, uA01);
      lA23 = add2(lA23, uA23);
      lB01 = add2(lB01, uB01);
      lB23 = add2(lB23, uB23);

      // P -> bf16 A fragment (register chaining)
      uint32_t pa[4];
      pa[0] = cvt_bf16x2(uA01);
      pa[1] = cvt_bf16x2(uA23);
      pa[2] = cvt_bf16x2(uB01);
      pa[3] = cvt_bf16x2(uB23);

      mma_bf16(oa0, pa, vv[0], vv[1]);   // dims 0-7
      mma_bf16(oa1, pa, vv[2], vv[3]);   // dims 8-15
    }

    if (kb < 24){
      uint32_t d = dstK + (uint32_t)(((kb+1) & 1)*2048);
      sts64(d, cvt_bf16x2_ff(nv.x, nv.y), cvt_bf16x2_ff(nv.z, nv.w));
    }
    __syncthreads();
  }

  // ---- epilogue ----
  float2 fA01 = unpack2(lA01), fA23 = unpack2(lA23);
  float2 fB01 = unpack2(lB01), fB23 = unpack2(lB23);
  float lr0 = fA01.x + fA01.y + fB01.x + fB01.y;
  float lr8 = fA23.x + fA23.y + fB23.x + fB23.y;
  lr0 += __shfl_xor_sync(0xffffffffu, lr0, 1);
  lr0 += __shfl_xor_sync(0xffffffffu, lr0, 2);
  lr8 += __shfl_xor_sync(0xffffffffu, lr8, 1);
  lr8 += __shfl_xor_sync(0xffffffffu, lr8, 2);
  float inv0 = 1.0f / (1600.0f + lr0);
  float inv8 = 1.0f / (1600.0f + lr8);

  if (wstore){
    const float* m0p = g_m0 + (b*NHEAD + h)*16;
    float* outb = g_attn + (b*HW + qbase)*DM + h*DH;
    float* oas[2] = {oa0, oa1};
    #pragma unroll
    for (int nt=0; nt<2; nt++){
      int d0 = nt*8 + 2*tig;
      float m0a = m0p[d0], m0b = m0p[d0+1];
      outb[(gid  )*DM + d0    ] = (oas[nt][0] + m0a) * inv0;
      outb[(gid  )*DM + d0 + 1] = (oas[nt][1] + m0b) * inv0;
      outb[(gid+8)*DM + d0    ] = (oas[nt][2] + m0a) * inv8;
      outb[(gid+8)*DM + d0 + 1] = (oas[nt][3] + m0b) * inv8;
    }
  }
}

// ---------------- K4: img_out = attn @ W2 + b2, transposed write + GeM partials
__global__ __launch_bounds__(256) void gemm2_kernel(const float* __restrict__ W2,
                                                    const float* __restrict__ b2,
                                                    float* __restrict__ img_out){
  __shared__ float As[64][33];
  __shared__ float Ws[32][128];
  __shared__ float colsum[128];
  int tile = blockIdx.x, ct = blockIdx.y;
  int b = tile / 25, pbase = (tile % 25) * 64;
  int tid = threadIdx.x, rgrp = tid >> 5, lane = tid & 31;
  if (tid < 128) colsum[tid] = 0.f;
  float acc[8][4];
  #pragma unroll
  for (int i=0;i<8;i++){ acc[i][0]=0.f; acc[i][1]=0.f; acc[i][2]=0.f; acc[i][3]=0.f; }

  for (int kt=0; kt<4; kt++){
    __syncthreads();
    #pragma unroll
    for (int it=0; it<2; it++){
      int idx = tid + it*256;
      int k4 = idx & 7, r = idx >> 3;
      float4 v = *(const float4*)(g_attn + (tile*64 + r)*DM + kt*32 + k4*4);
      As[r][k4*4+0]=v.x; As[r][k4*4+1]=v.y; As[r][k4*4+2]=v.z; As[r][k4*4+3]=v.w;
    }
    #pragma unroll
    for (int it=0; it<4; it++){
      int idx = tid + it*256;
      int c4 = idx & 31, k = idx >> 5;
      *(float4*)&Ws[k][c4*4] = *(const float4*)(W2 + (kt*32+k)*CI + ct*128 + c4*4);
    }
    __syncthreads();
    #pragma unroll 8
    for (int k=0;k<32;k++){
      float4 w = *(float4*)&Ws[k][lane*4];
      #pragma unroll
      for (int i=0;i<8;i++){
        float a = As[rgrp*8+i][k];
        acc[i][0] = fmaf(a, w.x, acc[i][0]);
        acc[i][1] = fmaf(a, w.y, acc[i][1]);
        acc[i][2] = fmaf(a, w.z, acc[i][2]);
        acc[i][3] = fmaf(a, w.w, acc[i][3]);
      }
    }
  }
  float4 bb = *(const float4*)(b2 + ct*128 + lane*4);
  float bv[4] = {bb.x, bb.y, bb.z, bb.w};
  #pragma unroll
  for (int j=0;j<4;j++){
    float part = 0.f; float vs[8];
    #pragma unroll
    for (int i=0;i<8;i++){
      float v = acc[i][j] + bv[j];
      vs[i] = v;
      float c = fmaxf(v, 1e-6f);
      part = fmaf(c*c, c, part);
    }
    atomicAdd(&colsum[lane*4+j], part);
    int cg = ct*128 + lane*4 + j;
    float* dst = img_out + b*CI*HW + cg*HW + pbase + rgrp*8;
    *(float4*)(dst)     = make_float4(vs[0],vs[1],vs[2],vs[3]);
    *(float4*)(dst + 4) = make_float4(vs[4],vs[5],vs[6],vs[7]);
  }
  __syncthreads();
  if (tid < 128) atomicAdd(&g_imgacc[b*CI + ct*128 + tid], colsum[tid]);
}

// ---------------- K7: cloud l2norm + segmented clamp^3 sum -------------------
// 512 blocks, 8 rows per warp (latency-bound fix: >3 CTAs/SM)
__global__ __launch_bounds__(256) void cloud_kernel(const float* __restrict__ cf,
                                                    const int* __restrict__ bids,
                                                    float* __restrict__ cloud_out){
  __shared__ float sseg[NB*DM];
  __shared__ float scnt[NB];
  int tid = threadIdx.x;
  for (int i=tid; i<NB*DM; i+=256) sseg[i] = 0.f;
  if (tid < NB) scnt[tid] = 0.f;
  __syncthreads();
  int w = tid >> 5, lane = tid & 31;
  int rbase = blockIdx.x*64 + w*8;
  #pragma unroll
  for (int i=0;i<8;i++){
    int row = rbase + i;
    int bid = bids[row];
    float4 v = *(const float4*)(cf + row*DM + lane*4);
    float sq = v.x*v.x + v.y*v.y + v.z*v.z + v.w*v.w;
    #pragma unroll
    for (int off=16; off; off>>=1) sq += __shfl_xor_sync(0xffffffffu, sq, off);
    float inv = 1.0f / fmaxf(sqrtf(sq), 1e-12f);
    float x0=v.x*inv, x1=v.y*inv, x2=v.z*inv, x3=v.w*inv;
    *(float4*)(cloud_out + row*DM + lane*4) = make_float4(x0,x1,x2,x3);
    float c0=fmaxf(x0,1e-6f), c1=fmaxf(x1,1e-6f), c2=fmaxf(x2,1e-6f), c3=fmaxf(x3,1e-6f);
    float* sp = sseg + bid*DM + lane*4;
    atomicAdd(sp+0, c0*c0*c0);
    atomicAdd(sp+1, c1*c1*c1);
    atomicAdd(sp+2, c2*c2*c2);
    atomicAdd(sp+3, c3*c3*c3);
    if (lane == 0) atomicAdd(&scnt[bid], 1.0f);
  }
  __syncthreads();
  for (int i=tid; i<NB*DM; i+=256) atomicAdd(&g_seg[i], sseg[i]);
  if (tid < NB) atomicAdd(&g_cnt[tid], scnt[tid]);
}

// ---------------- K8: finalize GeM outputs ----------------
__global__ void finalize_kernel(float* __restrict__ image_gem, float* __restrict__ cloud_gem){
  int i = blockIdx.x*256 + threadIdx.x;
  if (i < NB*CI) image_gem[i] = cbrtf(g_imgacc[i] * (1.0f/1600.0f));
  if (i < NB*DM) cloud_gem[i] = cbrtf(g_seg[i] / fmaxf(g_cnt[i>>7], 1.0f));
}

// ---------------- launch ----------------
extern "C" void kernel_launch(void* const* d_in, const int* in_sizes, int n_in,
                              void* d_out, int out_size){
  const float* img  = (const float*)d_in[0];
  const float* cf   = (const float*)d_in[1];
  const int*   bids = (const int*)  d_in[2];
  const float* W1   = (const float*)d_in[3];
  const float* b1   = (const float*)d_in[4];
  const float* W2   = (const float*)d_in[5];
  const float* b2   = (const float*)d_in[6];

  float* out       = (float*)d_out;
  float* img_out   = out;                                  // 8*256*1600
  float* cloud_out = out + (size_t)NB*CI*HW;               // 32768*128
  float* image_gem = cloud_out + (size_t)NCLOUD*DM;        // 2048
  float* cloud_gem = image_gem + NB*CI;                    // 1024

  zero_kernel<<<8, 256>>>();
  gemm1_kernel<<<200, 256>>>(img, W1, b1);
  m0_kernel<<<NB*NHEAD, 128>>>();
  attn_bf16_kernel<<<dim3(13, NHEAD, NB), 256>>>();
  gemm2_kernel<<<dim3(200, 2), 256>>>(W2, b2, img_out);
  cloud_kernel<<<512, 256>>>(cf, bids, cloud_out);
  finalize_kernel<<<8, 256>>>(image_gem, cloud_gem);
}

// round 11
// speedup vs baseline: 1.1643x; 1.1636x over previous
#include <cuda_runtime.h>
#include <cuda_bf16.h>
#include <cstdint>

// ---------------- constants ----------------
#define NB      8
#define CI      256
#define HW      1600
#define DM      128
#define NHEAD   8
#define DH      16
#define NROWS   (NB*HW)        // 12800
#define NCLOUD  32768

// ---------------- device scratch ----------------
__device__ float g_tok [NROWS*DM];     // l2-normalized image tokens
__device__ float g_attn[NROWS*DM];     // attention output
__device__ float g_m0  [NB*NHEAD*DH];  // per (b,h) sum of v over keys
__device__ float g_imgacc[NB*CI];
__device__ float g_seg  [NB*DM];
__device__ float g_cnt  [NB];

typedef unsigned long long u64;

// ---------------- packed f32x2 helpers ----------------
__device__ __forceinline__ u64 fma2(u64 a, u64 b, u64 c){
  u64 d; asm("fma.rn.f32x2 %0, %1, %2, %3;" : "=l"(d) : "l"(a), "l"(b), "l"(c)); return d;
}
__device__ __forceinline__ u64 mul2(u64 a, u64 b){
  u64 d; asm("mul.rn.f32x2 %0, %1, %2;" : "=l"(d) : "l"(a), "l"(b)); return d;
}
__device__ __forceinline__ u64 add2(u64 a, u64 b){
  u64 d; asm("add.rn.f32x2 %0, %1, %2;" : "=l"(d) : "l"(a), "l"(b)); return d;
}
__device__ __forceinline__ u64 pack2(float x, float y){
  u64 d; asm("mov.b64 %0, {%1, %2};" : "=l"(d) : "f"(x), "f"(y)); return d;
}
__device__ __forceinline__ float2 unpack2(u64 u){
  float2 f; asm("mov.b64 {%0, %1}, %2;" : "=f"(f.x), "=f"(f.y) : "l"(u)); return f;
}

// bf16x2 pack: lower = f.x, upper = f.y
__device__ __forceinline__ uint32_t cvt_bf16x2(u64 p){
  float2 f = unpack2(p);
  uint32_t r;
  asm("cvt.rn.bf16x2.f32 %0, %1, %2;" : "=r"(r) : "f"(f.y), "f"(f.x));
  return r;
}
__device__ __forceinline__ uint32_t cvt_bf16x2_ff(float lo, float hi){
  uint32_t r;
  asm("cvt.rn.bf16x2.f32 %0, %1, %2;" : "=r"(r) : "f"(hi), "f"(lo));
  return r;
}
__device__ __forceinline__ uint32_t packbf(__nv_bfloat16 a, __nv_bfloat16 b){
  __nv_bfloat162 t(a, b);
  return *reinterpret_cast<uint32_t*>(&t);
}

// ---------------- mma / ldmatrix helpers ----------------
__device__ __forceinline__ void mma_bf16(float* c, const uint32_t* a, uint32_t b0, uint32_t b1){
  asm volatile("mma.sync.aligned.m16n8k16.row.col.f32.bf16.bf16.f32 "
      "{%0,%1,%2,%3}, {%4,%5,%6,%7}, {%8,%9}, {%0,%1,%2,%3};"
      : "+f"(c[0]), "+f"(c[1]), "+f"(c[2]), "+f"(c[3])
      : "r"(a[0]), "r"(a[1]), "r"(a[2]), "r"(a[3]), "r"(b0), "r"(b1));
}
__device__ __forceinline__ void ldsm4(uint32_t addr, uint32_t* r){
  asm volatile("ldmatrix.sync.aligned.m8n8.x4.shared.b16 {%0,%1,%2,%3}, [%4];"
      : "=r"(r[0]), "=r"(r[1]), "=r"(r[2]), "=r"(r[3]) : "r"(addr));
}
__device__ __forceinline__ void ldsm4t(uint32_t addr, uint32_t* r){
  asm volatile("ldmatrix.sync.aligned.m8n8.x4.trans.shared.b16 {%0,%1,%2,%3}, [%4];"
      : "=r"(r[0]), "=r"(r[1]), "=r"(r[2]), "=r"(r[3]) : "r"(addr));
}
__device__ __forceinline__ void sts64(uint32_t addr, uint32_t r0, uint32_t r1){
  asm volatile("st.shared.v2.b32 [%0], {%1,%2};" :: "r"(addr), "r"(r0), "r"(r1));
}

// split pair of floats to hi/lo bf16x2
__device__ __forceinline__ void split2(float x0, float x1, uint32_t& hi, uint32_t& lo){
  __nv_bfloat16 h0 = __float2bfloat16_rn(x0);
  __nv_bfloat16 h1 = __float2bfloat16_rn(x1);
  float r0 = x0 - __bfloat162float(h0);
  float r1 = x1 - __bfloat162float(h1);
  hi = packbf(h0, h1);
  lo = packbf(__float2bfloat16_rn(r0), __float2bfloat16_rn(r1));
}

// ---------------- K0: zero accumulators ----------------
__global__ void zero_kernel(){
  int i = blockIdx.x*256 + threadIdx.x;
  if (i < NB*CI) g_imgacc[i] = 0.f;
  if (i < NB*DM) g_seg[i]    = 0.f;
  if (i < NB)    g_cnt[i]    = 0.f;
}

// ---------------- K1: x = einsum(bchw,cd)+b1, rowwise l2norm -> g_tok --------
__global__ __launch_bounds__(256) void gemm1_kernel(const float* __restrict__ img,
                                                    const float* __restrict__ W1,
                                                    const float* __restrict__ b1){
  __shared__ float As[32][64];
  __shared__ float Ws[32][128];
  int tile = blockIdx.x;
  int b = tile / 25;
  int pbase = (tile % 25) * 64;
  const float* Ab = img + b*CI*HW + pbase;
  int tid = threadIdx.x;
  int rgrp = tid >> 5, lane = tid & 31;
  float acc[8][4];
  #pragma unroll
  for (int i=0;i<8;i++){ acc[i][0]=0.f; acc[i][1]=0.f; acc[i][2]=0.f; acc[i][3]=0.f; }

  for (int kt=0; kt<8; kt++){
    __syncthreads();
    #pragma unroll
    for (int it=0; it<8; it++){
      int idx = tid + it*256;
      int r = idx & 63, k = idx >> 6;
      As[k][r] = Ab[(kt*32+k)*HW + r];
    }
    #pragma unroll
    for (int it=0; it<4; it++){
      int idx = tid + it*256;
      int c4 = idx & 31, k = idx >> 5;
      *(float4*)&Ws[k][c4*4] = *(const float4*)(W1 + (kt*32+k)*DM + c4*4);
    }
    __syncthreads();
    #pragma unroll 8
    for (int k=0;k<32;k++){
      float4 w  = *(float4*)&Ws[k][lane*4];
      float4 a0 = *(float4*)&As[k][rgrp*8];
      float4 a1 = *(float4*)&As[k][rgrp*8+4];
      float a[8] = {a0.x,a0.y,a0.z,a0.w,a1.x,a1.y,a1.z,a1.w};
      #pragma unroll
      for (int i=0;i<8;i++){
        acc[i][0] = fmaf(a[i], w.x, acc[i][0]);
        acc[i][1] = fmaf(a[i], w.y, acc[i][1]);
        acc[i][2] = fmaf(a[i], w.z, acc[i][2]);
        acc[i][3] = fmaf(a[i], w.w, acc[i][3]);
      }
    }
  }
  float4 bb = *(const float4*)(b1 + lane*4);
  int Rbase = tile*64 + rgrp*8;
  #pragma unroll
  for (int i=0;i<8;i++){
    float x0 = acc[i][0]+bb.x, x1 = acc[i][1]+bb.y, x2 = acc[i][2]+bb.z, x3 = acc[i][3]+bb.w;
    float sq = x0*x0 + x1*x1 + x2*x2 + x3*x3;
    #pragma unroll
    for (int off=16; off; off>>=1) sq += __shfl_xor_sync(0xffffffffu, sq, off);
    float inv = 1.0f / fmaxf(sqrtf(sq), 1e-12f);
    *(float4*)(g_tok + (Rbase+i)*DM + lane*4) = make_float4(x0*inv, x1*inv, x2*inv, x3*inv);
  }
}

// ---------------- K2: M0[b,h,d] = sum over keys of v ----------------
__global__ __launch_bounds__(128) void m0_kernel(){
  int bh = blockIdx.x;
  const float* base = g_tok + (bh>>3)*HW*DM + (bh&7)*DH;
  __shared__ float red[128];
  int tid = threadIdx.x;
  int d = tid & 15, seg = tid >> 4;
  float s = 0.f;
  for (int t = seg; t < HW; t += 8) s += base[t*DM + d];
  red[tid] = s;
  __syncthreads();
  if (tid < 16){
    float a = 0.f;
    #pragma unroll
    for (int i=0;i<8;i++) a += red[tid + i*16];
    g_m0[bh*16 + tid] = a;
  }
}

// ---------------- K3: attention, bf16 q & k scores, split PV accumulators ----
__global__ __launch_bounds__(256) void attn_bf16_kernel(){
  __shared__ __align__(1024) unsigned char sbuf[2][2048];
  int b = blockIdx.z, h = blockIdx.y;
  int tid = threadIdx.x, w = tid >> 5, lane = tid & 31;
  int gid = lane >> 2, tig = lane & 3;
  const float* base = g_tok + b*HW*DM + h*DH;
  int qb0 = blockIdx.x*128 + w*16;
  bool wstore = (qb0 < HW);
  int qbase = wstore ? qb0 : (HW - 16);

  // ---- Q fragments, scaled by 0.25 (exact), plain bf16 ----
  uint32_t qh[4];
  #pragma unroll
  for (int i=0;i<4;i++){
    int row = qbase + gid + (i & 1)*8;
    int col = 2*tig + (i >> 1)*8;
    float2 v = *(const float2*)(base + row*DM + col);
    qh[i] = packbf(__float2bfloat16_rn(v.x*0.25f), __float2bfloat16_rn(v.y*0.25f));
  }

  // split PV accumulators (even/odd chunks) to break HMMA chains
  float oa0E[4] = {0.f,0.f,0.f,0.f};
  float oa1E[4] = {0.f,0.f,0.f,0.f};
  float oa0O[4] = {0.f,0.f,0.f,0.f};
  float oa1O[4] = {0.f,0.f,0.f,0.f};
  u64 lA01 = 0ULL, lA23 = 0ULL, lB01 = 0ULL, lB23 = 0ULL;

  const u64 C24 = pack2(4.1666667e-2f, 4.1666667e-2f);
  const u64 C6  = pack2(1.6666667e-1f, 1.6666667e-1f);
  const u64 CH  = pack2(0.5f, 0.5f);
  const u64 C1  = pack2(1.0f, 1.0f);

  uint32_t sb0 = (uint32_t)__cvta_generic_to_shared(&sbuf[0][0]);
  int r7 = lane & 7;
  uint32_t aScore = sb0 + (uint32_t)((r7 + ((lane >> 4) & 1)*8)*16 + ((lane >> 3) & 1)*1024);
  uint32_t aPV    = sb0 + (uint32_t)((r7 + ((lane >> 3) & 1)*8)*16 + ((lane >> 4) & 1)*1024);

  int key = tid >> 2, quarter = tid & 3;
  const float* gsrc = base + key*DM + quarter*4;
  uint32_t dstK = sb0 + (uint32_t)((quarter >> 1)*1024 + key*16 + (quarter & 1)*8);

  // prologue: tile 0 -> buffer 0
  {
    float4 v = *(const float4*)(gsrc);
    sts64(dstK, cvt_bf16x2_ff(v.x, v.y), cvt_bf16x2_ff(v.z, v.w));
  }
  __syncthreads();

  for (int kb=0; kb<25; kb++){
    float4 nv;
    if (kb < 24) nv = *(const float4*)(gsrc + (kb+1)*64*DM);
    uint32_t bufoff = (uint32_t)((kb & 1)*2048);
    uint32_t aS = aScore + bufoff;
    uint32_t aP = aPV + bufoff;

    #pragma unroll
    for (int ck=0; ck<4; ck++){
      uint32_t off = (uint32_t)(ck*256);
      uint32_t kh[4], vv[4];
      ldsm4 (aS + off, kh);
      ldsm4t(aP + off, vv);

      float cA[4] = {0.f,0.f,0.f,0.f};
      float cB[4] = {0.f,0.f,0.f,0.f};
      mma_bf16(cA, qh, kh[0], kh[1]);
      mma_bf16(cB, qh, kh[2], kh[3]);

      // u = expm1(t), deg-4, packed pairs
      u64 tA01 = pack2(cA[0], cA[1]);
      u64 tA23 = pack2(cA[2], cA[3]);
      u64 tB01 = pack2(cB[0], cB[1]);
      u64 tB23 = pack2(cB[2], cB[3]);
      u64 wA01 = fma2(tA01, C24, C6);
      u64 wA23 = fma2(tA23, C24, C6);
      u64 wB01 = fma2(tB01, C24, C6);
      u64 wB23 = fma2(tB23, C24, C6);
      wA01 = fma2(tA01, wA01, CH);  wA23 = fma2(tA23, wA23, CH);
      wB01 = fma2(tB01, wB01, CH);  wB23 = fma2(tB23, wB23, CH);
      wA01 = fma2(tA01, wA01, C1);  wA23 = fma2(tA23, wA23, C1);
      wB01 = fma2(tB01, wB01, C1);  wB23 = fma2(tB23, wB23, C1);
      u64 uA01 = mul2(tA01, wA01);
      u64 uA23 = mul2(tA23, wA23);
      u64 uB01 = mul2(tB01, wB01);
      u64 uB23 = mul2(tB23, wB23);
      lA01 = add2(lA01, uA01);
      lA23 = add2(lA23, uA23);
      lB01 = add2(lB01, uB01);
      lB23 = add2(lB23, uB23);

      uint32_t pa[4];
      pa[0] = cvt_bf16x2(uA01);
      pa[1] = cvt_bf16x2(uA23);
      pa[2] = cvt_bf16x2(uB01);
      pa[3] = cvt_bf16x2(uB23);

      if (ck & 1){
        mma_bf16(oa0O, pa, vv[0], vv[1]);
        mma_bf16(oa1O, pa, vv[2], vv[3]);
      } else {
        mma_bf16(oa0E, pa, vv[0], vv[1]);
        mma_bf16(oa1E, pa, vv[2], vv[3]);
      }
    }

    if (kb < 24){
      uint32_t d = dstK + (uint32_t)(((kb+1) & 1)*2048);
      sts64(d, cvt_bf16x2_ff(nv.x, nv.y), cvt_bf16x2_ff(nv.z, nv.w));
    }
    __syncthreads();
  }

  // ---- epilogue ----
  float oa0[4], oa1[4];
  #pragma unroll
  for (int i=0;i<4;i++){ oa0[i] = oa0E[i] + oa0O[i]; oa1[i] = oa1E[i] + oa1O[i]; }
  float2 fA01 = unpack2(lA01), fA23 = unpack2(lA23);
  float2 fB01 = unpack2(lB01), fB23 = unpack2(lB23);
  float lr0 = fA01.x + fA01.y + fB01.x + fB01.y;
  float lr8 = fA23.x + fA23.y + fB23.x + fB23.y;
  lr0 += __shfl_xor_sync(0xffffffffu, lr0, 1);
  lr0 += __shfl_xor_sync(0xffffffffu, lr0, 2);
  lr8 += __shfl_xor_sync(0xffffffffu, lr8, 1);
  lr8 += __shfl_xor_sync(0xffffffffu, lr8, 2);
  float inv0 = 1.0f / (1600.0f + lr0);
  float inv8 = 1.0f / (1600.0f + lr8);

  if (wstore){
    const float* m0p = g_m0 + (b*NHEAD + h)*16;
    float* outb = g_attn + (b*HW + qbase)*DM + h*DH;
    float* oas[2] = {oa0, oa1};
    #pragma unroll
    for (int nt=0; nt<2; nt++){
      int d0 = nt*8 + 2*tig;
      float m0a = m0p[d0], m0b = m0p[d0+1];
      outb[(gid  )*DM + d0    ] = (oas[nt][0] + m0a) * inv0;
      outb[(gid  )*DM + d0 + 1] = (oas[nt][1] + m0b) * inv0;
      outb[(gid+8)*DM + d0    ] = (oas[nt][2] + m0a) * inv8;
      outb[(gid+8)*DM + d0 + 1] = (oas[nt][3] + m0b) * inv8;
    }
  }
}

// ---------------- K4: gemm2 via split-bf16 mma ----------------
// img_out = attn @ W2 + b2 (transposed write) + GeM partials.
// 64 rows x 256 cols per CTA, 8 warps: warp w -> m-sub (w&3)*16, n-half (w>>2)*128.
// A planes: [row 64][kc 16 ^ swz][16B], plane 16 KB. W staged per 16-k:
// [k 16][nc 32 ^ swz][16B], plane 8 KB. Total smem = 48 KB exactly.
__global__ __launch_bounds__(256, 2) void gemm2_mma_kernel(const float* __restrict__ W2,
                                                           const float* __restrict__ b2,
                                                           float* __restrict__ img_out){
  __shared__ __align__(1024) unsigned char sA[2][16384];   // hi/lo planes
  __shared__ __align__(1024) unsigned char sW[2][8192];    // hi/lo planes (one 16-k stage)
  int tile = blockIdx.x;
  int b = tile / 25, pbase = (tile % 25) * 64;
  int tid = threadIdx.x, w = tid >> 5, lane = tid & 31;
  int gid = lane >> 2, tig = lane & 3, r7 = lane & 7;

  uint32_t sa0 = (uint32_t)__cvta_generic_to_shared(&sA[0][0]);
  uint32_t sw0 = (uint32_t)__cvta_generic_to_shared(&sW[0][0]);

  // ---- load A tile (64 rows x 128 k, f32) -> split planes ----
  {
    const float* Abase = g_attn + (size_t)(tile*64)*DM;
    #pragma unroll
    for (int it=0; it<8; it++){
      int idx = tid + it*256;           // 2048 float4s
      int r = idx >> 5, kc4 = idx & 31; // kc4: 4-float piece
      int kc = kc4 >> 1, half = kc4 & 1;
      float4 v = *(const float4*)(Abase + r*DM + kc4*4);
      uint32_t h0, l0, h1, l1;
      split2(v.x, v.y, h0, l0);
      split2(v.z, v.w, h1, l1);
      uint32_t addr = sa0 + (uint32_t)(r*256 + ((kc ^ r7 ^ (r & 7) ^ r7) & 15)*16 + half*8);
      // swizzle: kc' = kc ^ (r&7)
      addr = sa0 + (uint32_t)(r*256 + ((kc ^ (r & 7)))*16 + half*8);
      sts64(addr,         h0, h1);
      sts64(addr + 16384, l0, l1);
    }
  }

  // accumulators: 16 n-chunks x 4
  float oa[16][4];
  #pragma unroll
  for (int i=0;i<16;i++){ oa[i][0]=0.f; oa[i][1]=0.f; oa[i][2]=0.f; oa[i][3]=0.f; }

  // ldsm A address lane-part: row = (w&3)*16 + r7 + ((lane>>3)&1)*8
  int arow = (w & 3)*16 + r7 + ((lane >> 3) & 1)*8;
  // ldsm W lane-part: klocal = r7 + ((lane>>3)&1)*8 ; nc = nc0 + (lane>>4)
  int klocal = r7 + ((lane >> 3) & 1)*8;
  int ncsel  = (lane >> 4) & 1;
  int nbase  = (w >> 2) * 16;          // n-chunk base for this warp

  for (int ks=0; ks<8; ks++){
    // prefetch W stage (16 k x 256 n f32) into regs
    float4 wreg[4];
    #pragma unroll
    for (int it=0; it<4; it++){
      int idx = tid + it*256;           // 1024 float4s
      int kk = idx >> 6, nc4 = idx & 63;
      wreg[it] = *(const float4*)(W2 + (ks*16 + kk)*CI + nc4*4);
    }
    __syncthreads();   // all warps done reading previous W stage
    #pragma unroll
    for (int it=0; it<4; it++){
      int idx = tid + it*256;
      int kk = idx >> 6, nc4 = idx & 63;
      int nc = nc4 >> 1, half = nc4 & 1;
      uint32_t h0, l0, h1, l1;
      split2(wreg[it].x, wreg[it].y, h0, l0);
      split2(wreg[it].z, wreg[it].w, h1, l1);
      uint32_t addr = sw0 + (uint32_t)(kk*512 + (nc ^ (kk & 7))*16 + half*8);
      sts64(addr,        h0, h1);
      sts64(addr + 8192, l0, l1);
    }
    __syncthreads();

    // A fragments for this k-step
    uint32_t ah[4], al[4];
    {
      int kcv = 2*ks + ((lane >> 4) & 1);
      uint32_t aaddr = sa0 + (uint32_t)(arow*256 + ((kcv ^ r7))*16);
      ldsm4(aaddr, ah);
      ldsm4(aaddr + 16384, al);
    }

    #pragma unroll
    for (int p=0; p<8; p++){
      int nc0 = nbase + 2*p;
      uint32_t waddr = sw0 + (uint32_t)(klocal*512 + (((nc0 + ncsel) ^ r7))*16);
      uint32_t wh[4], wl[4];
      ldsm4t(waddr, wh);
      ldsm4t(waddr + 8192, wl);
      mma_bf16(oa[2*p],   ah, wh[0], wh[1]);
      mma_bf16(oa[2*p],   ah, wl[0], wl[1]);
      mma_bf16(oa[2*p],   al, wh[0], wh[1]);
      mma_bf16(oa[2*p+1], ah, wh[2], wh[3]);
      mma_bf16(oa[2*p+1], ah, wl[2], wl[3]);
      mma_bf16(oa[2*p+1], al, wh[2], wh[3]);
    }
  }

  // ---- epilogue: bias, transposed store, GeM partials ----
  int p0 = pbase + (w & 3)*16 + gid;
  float* outB = img_out + (size_t)b*CI*HW;
  #pragma unroll
  for (int nc=0; nc<16; nc++){
    int c0 = (w >> 2)*128 + nc*8 + 2*tig;
    float bb0 = __ldg(b2 + c0), bb1 = __ldg(b2 + c0 + 1);
    float v00 = oa[nc][0] + bb0, v01 = oa[nc][1] + bb1;
    float v10 = oa[nc][2] + bb0, v11 = oa[nc][3] + bb1;
    outB[(size_t)c0*HW + p0]           = v00;
    outB[(size_t)(c0+1)*HW + p0]       = v01;
    outB[(size_t)c0*HW + p0 + 8]       = v10;
    outB[(size_t)(c0+1)*HW + p0 + 8]   = v11;
    float e00 = fmaxf(v00, 1e-6f), e01 = fmaxf(v01, 1e-6f);
    float e10 = fmaxf(v10, 1e-6f), e11 = fmaxf(v11, 1e-6f);
    float pc0 = e00*e00*e00 + e10*e10*e10;
    float pc1 = e01*e01*e01 + e11*e11*e11;
    // reduce over gid (lanes stride 4)
    pc0 += __shfl_xor_sync(0xffffffffu, pc0, 4);
    pc1 += __shfl_xor_sync(0xffffffffu, pc1, 4);
    pc0 += __shfl_xor_sync(0xffffffffu, pc0, 8);
    pc1 += __shfl_xor_sync(0xffffffffu, pc1, 8);
    pc0 += __shfl_xor_sync(0xffffffffu, pc0, 16);
    pc1 += __shfl_xor_sync(0xffffffffu, pc1, 16);
    if (lane < 4){
      atomicAdd(&g_imgacc[b*CI + c0],     pc0);
      atomicAdd(&g_imgacc[b*CI + c0 + 1], pc1);
    }
  }
}

// ---------------- K7: cloud l2norm + segmented clamp^3 sum -------------------
__global__ __launch_bounds__(256) void cloud_kernel(const float* __restrict__ cf,
                                                    const int* __restrict__ bids,
                                                    float* __restrict__ cloud_out){
  __shared__ float sseg[NB*DM];
  __shared__ float scnt[NB];
  int tid = threadIdx.x;
  for (int i=tid; i<NB*DM; i+=256) sseg[i] = 0.f;
  if (tid < NB) scnt[tid] = 0.f;
  __syncthreads();
  int w = tid >> 5, lane = tid & 31;
  int rbase = blockIdx.x*64 + w*8;
  #pragma unroll
  for (int i=0;i<8;i++){
    int row = rbase + i;
    int bid = bids[row];
    float4 v = *(const float4*)(cf + row*DM + lane*4);
    float sq = v.x*v.x + v.y*v.y + v.z*v.z + v.w*v.w;
    #pragma unroll
    for (int off=16; off; off>>=1) sq += __shfl_xor_sync(0xffffffffu, sq, off);
    float inv = 1.0f / fmaxf(sqrtf(sq), 1e-12f);
    float x0=v.x*inv, x1=v.y*inv, x2=v.z*inv, x3=v.w*inv;
    *(float4*)(cloud_out + row*DM + lane*4) = make_float4(x0,x1,x2,x3);
    float c0=fmaxf(x0,1e-6f), c1=fmaxf(x1,1e-6f), c2=fmaxf(x2,1e-6f), c3=fmaxf(x3,1e-6f);
    float* sp = sseg + bid*DM + lane*4;
    atomicAdd(sp+0, c0*c0*c0);
    atomicAdd(sp+1, c1*c1*c1);
    atomicAdd(sp+2, c2*c2*c2);
    atomicAdd(sp+3, c3*c3*c3);
    if (lane == 0) atomicAdd(&scnt[bid], 1.0f);
  }
  __syncthreads();
  for (int i=tid; i<NB*DM; i+=256) atomicAdd(&g_seg[i], sseg[i]);
  if (tid < NB) atomicAdd(&g_cnt[tid], scnt[tid]);
}

// ---------------- K8: finalize GeM outputs ----------------
__global__ void finalize_kernel(float* __restrict__ image_gem, float* __restrict__ cloud_gem){
  int i = blockIdx.x*256 + threadIdx.x;
  if (i < NB*CI) image_gem[i] = cbrtf(g_imgacc[i] * (1.0f/1600.0f));
  if (i < NB*DM) cloud_gem[i] = cbrtf(g_seg[i] / fmaxf(g_cnt[i>>7], 1.0f));
}

// ---------------- launch ----------------
extern "C" void kernel_launch(void* const* d_in, const int* in_sizes, int n_in,
                              void* d_out, int out_size){
  const float* img  = (const float*)d_in[0];
  const float* cf   = (const float*)d_in[1];
  const int*   bids = (const int*)  d_in[2];
  const float* W1   = (const float*)d_in[3];
  const float* b1   = (const float*)d_in[4];
  const float* W2   = (const float*)d_in[5];
  const float* b2   = (const float*)d_in[6];

  float* out       = (float*)d_out;
  float* img_out   = out;                                  // 8*256*1600
  float* cloud_out = out + (size_t)NB*CI*HW;               // 32768*128
  float* image_gem = cloud_out + (size_t)NCLOUD*DM;        // 2048
  float* cloud_gem = image_gem + NB*CI;                    // 1024

  zero_kernel<<<8, 256>>>();
  gemm1_kernel<<<200, 256>>>(img, W1, b1);
  m0_kernel<<<NB*NHEAD, 128>>>();
  attn_bf16_kernel<<<dim3(13, NHEAD, NB), 256>>>();
  gemm2_mma_kernel<<<200, 256>>>(W2, b2, img_out);
  cloud_kernel<<<512, 256>>>(cf, bids, cloud_out);
  finalize_kernel<<<8, 256>>>(image_gem, cloud_gem);
}

// round 12
// speedup vs baseline: 1.3946x; 1.1978x over previous
#include <cuda_runtime.h>
#include <cuda_bf16.h>
#include <cstdint>

// ---------------- constants ----------------
#define NB      8
#define CI      256
#define HW      1600
#define DM      128
#define NHEAD   8
#define DH      16
#define NROWS   (NB*HW)        // 12800
#define NCLOUD  32768

// ---------------- device scratch ----------------
__device__ float g_tok [NROWS*DM];     // l2-normalized image tokens
__device__ float g_attn[NROWS*DM];     // attention output
__device__ float g_m0  [NB*DM];        // per (b, dim) sum of normalized tokens
__device__ float g_imgacc[NB*CI];
__device__ float g_seg  [NB*DM];
__device__ float g_cnt  [NB];

typedef unsigned long long u64;

// ---------------- packed f32x2 helpers ----------------
__device__ __forceinline__ u64 fma2(u64 a, u64 b, u64 c){
  u64 d; asm("fma.rn.f32x2 %0, %1, %2, %3;" : "=l"(d) : "l"(a), "l"(b), "l"(c)); return d;
}
__device__ __forceinline__ u64 mul2(u64 a, u64 b){
  u64 d; asm("mul.rn.f32x2 %0, %1, %2;" : "=l"(d) : "l"(a), "l"(b)); return d;
}
__device__ __forceinline__ u64 add2(u64 a, u64 b){
  u64 d; asm("add.rn.f32x2 %0, %1, %2;" : "=l"(d) : "l"(a), "l"(b)); return d;
}
__device__ __forceinline__ u64 pack2(float x, float y){
  u64 d; asm("mov.b64 %0, {%1, %2};" : "=l"(d) : "f"(x), "f"(y)); return d;
}
__device__ __forceinline__ float2 unpack2(u64 u){
  float2 f; asm("mov.b64 {%0, %1}, %2;" : "=f"(f.x), "=f"(f.y) : "l"(u)); return f;
}

// bf16x2 pack: lower = f.x, upper = f.y
__device__ __forceinline__ uint32_t cvt_bf16x2(u64 p){
  float2 f = unpack2(p);
  uint32_t r;
  asm("cvt.rn.bf16x2.f32 %0, %1, %2;" : "=r"(r) : "f"(f.y), "f"(f.x));
  return r;
}
__device__ __forceinline__ uint32_t cvt_bf16x2_ff(float lo, float hi){
  uint32_t r;
  asm("cvt.rn.bf16x2.f32 %0, %1, %2;" : "=r"(r) : "f"(hi), "f"(lo));
  return r;
}
__device__ __forceinline__ uint32_t packbf(__nv_bfloat16 a, __nv_bfloat16 b){
  __nv_bfloat162 t(a, b);
  return *reinterpret_cast<uint32_t*>(&t);
}

// ---------------- mma / ldmatrix helpers ----------------
__device__ __forceinline__ void mma_bf16(float* c, const uint32_t* a, uint32_t b0, uint32_t b1){
  asm volatile("mma.sync.aligned.m16n8k16.row.col.f32.bf16.bf16.f32 "
      "{%0,%1,%2,%3}, {%4,%5,%6,%7}, {%8,%9}, {%0,%1,%2,%3};"
      : "+f"(c[0]), "+f"(c[1]), "+f"(c[2]), "+f"(c[3])
      : "r"(a[0]), "r"(a[1]), "r"(a[2]), "r"(a[3]), "r"(b0), "r"(b1));
}
__device__ __forceinline__ void ldsm4(uint32_t addr, uint32_t* r){
  asm volatile("ldmatrix.sync.aligned.m8n8.x4.shared.b16 {%0,%1,%2,%3}, [%4];"
      : "=r"(r[0]), "=r"(r[1]), "=r"(r[2]), "=r"(r[3]) : "r"(addr));
}
__device__ __forceinline__ void ldsm4t(uint32_t addr, uint32_t* r){
  asm volatile("ldmatrix.sync.aligned.m8n8.x4.trans.shared.b16 {%0,%1,%2,%3}, [%4];"
      : "=r"(r[0]), "=r"(r[1]), "=r"(r[2]), "=r"(r[3]) : "r"(addr));
}
__device__ __forceinline__ void sts64(uint32_t addr, uint32_t r0, uint32_t r1){
  asm volatile("st.shared.v2.b32 [%0], {%1,%2};" :: "r"(addr), "r"(r0), "r"(r1));
}

// split pair of floats to hi/lo bf16x2
__device__ __forceinline__ void split2(float x0, float x1, uint32_t& hi, uint32_t& lo){
  __nv_bfloat16 h0 = __float2bfloat16_rn(x0);
  __nv_bfloat16 h1 = __float2bfloat16_rn(x1);
  float r0 = x0 - __bfloat162float(h0);
  float r1 = x1 - __bfloat162float(h1);
  hi = packbf(h0, h1);
  lo = packbf(__float2bfloat16_rn(r0), __float2bfloat16_rn(r1));
}

// ---------------- K0: zero accumulators ----------------
__global__ void zero_kernel(){
  int i = blockIdx.x*256 + threadIdx.x;
  if (i < NB*CI) g_imgacc[i] = 0.f;
  if (i < NB*DM){ g_seg[i] = 0.f; g_m0[i] = 0.f; }
  if (i < NB)    g_cnt[i]  = 0.f;
}

// ---------------- K1: gemm1 via split-bf16 mma + l2norm + M0 fusion ----------
// x = img^T @ W1 + b1 per batch; rows r=(b,p) tile of 64, cols 128.
// A stage: [k 16][r 64] bf16 planes (ldsm trans -> row-major A frags).
// W stage: [k 16][c 128] bf16 planes. 16 k-steps. Epilogue: smem f32 tile,
// rowwise l2 norm (exact f32), write g_tok, column sums -> g_m0 (atomics).
__global__ __launch_bounds__(256, 2) void gemm1_mma_kernel(const float* __restrict__ img,
                                                           const float* __restrict__ W1,
                                                           const float* __restrict__ b1){
  __shared__ __align__(128) unsigned char sAh[2048];
  __shared__ __align__(128) unsigned char sAl[2048];
  __shared__ __align__(128) unsigned char sWh[4096];
  __shared__ __align__(128) unsigned char sWl[4096];
  __shared__ __align__(16)  float sOut[64*132];
  int tile = blockIdx.x;
  int b = tile / 25, pbase = (tile % 25) * 64;
  int tid = threadIdx.x, w = tid >> 5, lane = tid & 31;
  int gid = lane >> 2, tig = lane & 3, r7 = lane & 7;

  uint32_t ah0 = (uint32_t)__cvta_generic_to_shared(sAh);
  uint32_t al0 = (uint32_t)__cvta_generic_to_shared(sAl);
  uint32_t wh0 = (uint32_t)__cvta_generic_to_shared(sWh);
  uint32_t wl0 = (uint32_t)__cvta_generic_to_shared(sWl);

  const float* Abase = img + b*CI*HW + pbase;   // + k*HW + r

  float oa[8][4];
  #pragma unroll
  for (int i=0;i<8;i++){ oa[i][0]=0.f; oa[i][1]=0.f; oa[i][2]=0.f; oa[i][3]=0.f; }

  // ldsm lane addressing
  int kkA = r7 + ((lane >> 4) & 1)*8;
  int uA  = (w & 3)*2 + ((lane >> 3) & 1);
  uint32_t aoff = (uint32_t)(kkA*128 + ((uA ^ (kkA & 7)))*16);
  int kkW = r7 + ((lane >> 3) & 1)*8;
  int nsel = (lane >> 4) & 1;
  int nbase8 = (w >> 2)*8;

  // stage-store indices
  int kkSa = tid >> 4, r4 = tid & 15;
  int kkSw = tid >> 5, c4 = tid & 31;
  int ncw = c4 >> 1, halfw = c4 & 1;
  uint32_t aSaddr  = (uint32_t)(kkSa*128 + (((r4 >> 1) ^ (kkSa & 7)))*16 + (r4 & 1)*8);
  uint32_t wSaddr0 = (uint32_t)(kkSw*256 + ((ncw ^ (kkSw & 7)))*16 + halfw*8);
  uint32_t wSaddr1 = (uint32_t)((kkSw+8)*256 + ((ncw ^ ((kkSw+8) & 7)))*16 + halfw*8);

  for (int ks=0; ks<16; ks++){
    // prefetch stage into registers
    float4 va  = *(const float4*)(Abase + (ks*16 + kkSa)*HW + r4*4);
    float4 vw0 = *(const float4*)(W1 + (ks*16 + kkSw)*DM + c4*4);
    float4 vw1 = *(const float4*)(W1 + (ks*16 + 8 + kkSw)*DM + c4*4);
    __syncthreads();                        // prior stage fully consumed
    {
      uint32_t h0,l0,h1,l1;
      split2(va.x, va.y, h0, l0); split2(va.z, va.w, h1, l1);
      sts64(ah0 + aSaddr, h0, h1);
      sts64(al0 + aSaddr, l0, l1);
      split2(vw0.x, vw0.y, h0, l0); split2(vw0.z, vw0.w, h1, l1);
      sts64(wh0 + wSaddr0, h0, h1);
      sts64(wl0 + wSaddr0, l0, l1);
      split2(vw1.x, vw1.y, h0, l0); split2(vw1.z, vw1.w, h1, l1);
      sts64(wh0 + wSaddr1, h0, h1);
      sts64(wl0 + wSaddr1, l0, l1);
    }
    __syncthreads();

    uint32_t ah[4], al[4];
    ldsm4t(ah0 + aoff, ah);
    ldsm4t(al0 + aoff, al);

    #pragma unroll
    for (int p=0; p<4; p++){
      int unit = nbase8 + 2*p + nsel;
      uint32_t waddr = (uint32_t)(kkW*256 + ((unit ^ (kkW & 7)))*16);
      uint32_t wh[4], wl[4];
      ldsm4t(wh0 + waddr, wh);
      ldsm4t(wl0 + waddr, wl);
      mma_bf16(oa[2*p],   ah, wh[0], wh[1]);
      mma_bf16(oa[2*p],   ah, wl[0], wl[1]);
      mma_bf16(oa[2*p],   al, wh[0], wh[1]);
      mma_bf16(oa[2*p+1], ah, wh[2], wh[3]);
      mma_bf16(oa[2*p+1], ah, wl[2], wl[3]);
      mma_bf16(oa[2*p+1], al, wh[2], wh[3]);
    }
  }
  __syncthreads();    // before reusing smem region for epilogue (sOut is separate, but keep order)

  // ---- spill f32 tile to smem ----
  {
    int r0 = (w & 3)*16 + gid;
    #pragma unroll
    for (int p=0; p<8; p++){
      int c0 = (w >> 2)*64 + p*8 + 2*tig;
      sOut[r0*132 + c0]       = oa[p][0];
      sOut[r0*132 + c0 + 1]   = oa[p][1];
      sOut[(r0+8)*132 + c0]   = oa[p][2];
      sOut[(r0+8)*132 + c0+1] = oa[p][3];
    }
  }
  __syncthreads();

  // ---- rowwise: add bias, l2 norm, write g_tok, keep normalized in smem ----
  {
    int r = tid >> 2, seg = tid & 3;
    float xv[32];
    float s = 0.f;
    float* op = sOut + r*132 + seg*32;
    const float* bp = b1 + seg*32;
    #pragma unroll
    for (int j4=0; j4<8; j4++){
      float4 xb = *(float4*)(op + j4*4);
      float4 bb = *(const float4*)(bp + j4*4);
      float x0 = xb.x + bb.x, x1 = xb.y + bb.y, x2 = xb.z + bb.z, x3 = xb.w + bb.w;
      xv[4*j4]=x0; xv[4*j4+1]=x1; xv[4*j4+2]=x2; xv[4*j4+3]=x3;
      s += x0*x0 + x1*x1 + x2*x2 + x3*x3;
    }
    s += __shfl_xor_sync(0xffffffffu, s, 1);
    s += __shfl_xor_sync(0xffffffffu, s, 2);
    float inv = 1.0f / fmaxf(sqrtf(s), 1e-12f);
    float* tp = g_tok + (size_t)(tile*64 + r)*DM + seg*32;
    #pragma unroll
    for (int j4=0; j4<8; j4++){
      float4 o = make_float4(xv[4*j4]*inv, xv[4*j4+1]*inv, xv[4*j4+2]*inv, xv[4*j4+3]*inv);
      *(float4*)(tp + j4*4) = o;
      *(float4*)(op + j4*4) = o;
    }
  }
  __syncthreads();

  // ---- column sums of normalized tile -> g_m0[b][dim] ----
  if (tid < 128){
    float cs = 0.f;
    #pragma unroll 8
    for (int r=0; r<64; r++) cs += sOut[r*132 + tid];
    atomicAdd(&g_m0[b*DM + tid], cs);
  }
}

// ---------------- K3: attention, bf16 q & k scores, split PV accumulators ----
__global__ __launch_bounds__(256) void attn_bf16_kernel(){
  __shared__ __align__(1024) unsigned char sbuf[2][2048];
  int b = blockIdx.z, h = blockIdx.y;
  int tid = threadIdx.x, w = tid >> 5, lane = tid & 31;
  int gid = lane >> 2, tig = lane & 3;
  const float* base = g_tok + b*HW*DM + h*DH;
  int qb0 = blockIdx.x*128 + w*16;
  bool wstore = (qb0 < HW);
  int qbase = wstore ? qb0 : (HW - 16);

  uint32_t qh[4];
  #pragma unroll
  for (int i=0;i<4;i++){
    int row = qbase + gid + (i & 1)*8;
    int col = 2*tig + (i >> 1)*8;
    float2 v = *(const float2*)(base + row*DM + col);
    qh[i] = packbf(__float2bfloat16_rn(v.x*0.25f), __float2bfloat16_rn(v.y*0.25f));
  }

  float oa0E[4] = {0.f,0.f,0.f,0.f};
  float oa1E[4] = {0.f,0.f,0.f,0.f};
  float oa0O[4] = {0.f,0.f,0.f,0.f};
  float oa1O[4] = {0.f,0.f,0.f,0.f};
  u64 lA01 = 0ULL, lA23 = 0ULL, lB01 = 0ULL, lB23 = 0ULL;

  const u64 C24 = pack2(4.1666667e-2f, 4.1666667e-2f);
  const u64 C6  = pack2(1.6666667e-1f, 1.6666667e-1f);
  const u64 CH  = pack2(0.5f, 0.5f);
  const u64 C1  = pack2(1.0f, 1.0f);

  uint32_t sb0 = (uint32_t)__cvta_generic_to_shared(&sbuf[0][0]);
  int r7 = lane & 7;
  uint32_t aScore = sb0 + (uint32_t)((r7 + ((lane >> 4) & 1)*8)*16 + ((lane >> 3) & 1)*1024);
  uint32_t aPV    = sb0 + (uint32_t)((r7 + ((lane >> 3) & 1)*8)*16 + ((lane >> 4) & 1)*1024);

  int key = tid >> 2, quarter = tid & 3;
  const float* gsrc = base + key*DM + quarter*4;
  uint32_t dstK = sb0 + (uint32_t)((quarter >> 1)*1024 + key*16 + (quarter & 1)*8);

  {
    float4 v = *(const float4*)(gsrc);
    sts64(dstK, cvt_bf16x2_ff(v.x, v.y), cvt_bf16x2_ff(v.z, v.w));
  }
  __syncthreads();

  for (int kb=0; kb<25; kb++){
    float4 nv;
    if (kb < 24) nv = *(const float4*)(gsrc + (kb+1)*64*DM);
    uint32_t bufoff = (uint32_t)((kb & 1)*2048);
    uint32_t aS = aScore + bufoff;
    uint32_t aP = aPV + bufoff;

    #pragma unroll
    for (int ck=0; ck<4; ck++){
      uint32_t off = (uint32_t)(ck*256);
      uint32_t kh[4], vv[4];
      ldsm4 (aS + off, kh);
      ldsm4t(aP + off, vv);

      float cA[4] = {0.f,0.f,0.f,0.f};
      float cB[4] = {0.f,0.f,0.f,0.f};
      mma_bf16(cA, qh, kh[0], kh[1]);
      mma_bf16(cB, qh, kh[2], kh[3]);

      u64 tA01 = pack2(cA[0], cA[1]);
      u64 tA23 = pack2(cA[2], cA[3]);
      u64 tB01 = pack2(cB[0], cB[1]);
      u64 tB23 = pack2(cB[2], cB[3]);
      u64 wA01 = fma2(tA01, C24, C6);
      u64 wA23 = fma2(tA23, C24, C6);
      u64 wB01 = fma2(tB01, C24, C6);
      u64 wB23 = fma2(tB23, C24, C6);
      wA01 = fma2(tA01, wA01, CH);  wA23 = fma2(tA23, wA23, CH);
      wB01 = fma2(tB01, wB01, CH);  wB23 = fma2(tB23, wB23, CH);
      wA01 = fma2(tA01, wA01, C1);  wA23 = fma2(tA23, wA23, C1);
      wB01 = fma2(tB01, wB01, C1);  wB23 = fma2(tB23, wB23, C1);
      u64 uA01 = mul2(tA01, wA01);
      u64 uA23 = mul2(tA23, wA23);
      u64 uB01 = mul2(tB01, wB01);
      u64 uB23 = mul2(tB23, wB23);
      lA01 = add2(lA01, uA01);
      lA23 = add2(lA23, uA23);
      lB01 = add2(lB01, uB01);
      lB23 = add2(lB23, uB23);

      uint32_t pa[4];
      pa[0] = cvt_bf16x2(uA01);
      pa[1] = cvt_bf16x2(uA23);
      pa[2] = cvt_bf16x2(uB01);
      pa[3] = cvt_bf16x2(uB23);

      if (ck & 1){
        mma_bf16(oa0O, pa, vv[0], vv[1]);
        mma_bf16(oa1O, pa, vv[2], vv[3]);
      } else {
        mma_bf16(oa0E, pa, vv[0], vv[1]);
        mma_bf16(oa1E, pa, vv[2], vv[3]);
      }
    }

    if (kb < 24){
      uint32_t d = dstK + (uint32_t)(((kb+1) & 1)*2048);
      sts64(d, cvt_bf16x2_ff(nv.x, nv.y), cvt_bf16x2_ff(nv.z, nv.w));
    }
    __syncthreads();
  }

  float oa0[4], oa1[4];
  #pragma unroll
  for (int i=0;i<4;i++){ oa0[i] = oa0E[i] + oa0O[i]; oa1[i] = oa1E[i] + oa1O[i]; }
  float2 fA01 = unpack2(lA01), fA23 = unpack2(lA23);
  float2 fB01 = unpack2(lB01), fB23 = unpack2(lB23);
  float lr0 = fA01.x + fA01.y + fB01.x + fB01.y;
  float lr8 = fA23.x + fA23.y + fB23.x + fB23.y;
  lr0 += __shfl_xor_sync(0xffffffffu, lr0, 1);
  lr0 += __shfl_xor_sync(0xffffffffu, lr0, 2);
  lr8 += __shfl_xor_sync(0xffffffffu, lr8, 1);
  lr8 += __shfl_xor_sync(0xffffffffu, lr8, 2);
  float inv0 = 1.0f / (1600.0f + lr0);
  float inv8 = 1.0f / (1600.0f + lr8);

  if (wstore){
    const float* m0p = g_m0 + b*DM + h*DH;
    float* outb = g_attn + (b*HW + qbase)*DM + h*DH;
    float* oas[2] = {oa0, oa1};
    #pragma unroll
    for (int nt=0; nt<2; nt++){
      int d0 = nt*8 + 2*tig;
      float m0a = m0p[d0], m0b = m0p[d0+1];
      outb[(gid  )*DM + d0    ] = (oas[nt][0] + m0a) * inv0;
      outb[(gid  )*DM + d0 + 1] = (oas[nt][1] + m0b) * inv0;
      outb[(gid+8)*DM + d0    ] = (oas[nt][2] + m0a) * inv8;
      outb[(gid+8)*DM + d0 + 1] = (oas[nt][3] + m0b) * inv8;
    }
  }
}

// ---------------- K4: gemm2 via split-bf16 mma ----------------
__global__ __launch_bounds__(256, 2) void gemm2_mma_kernel(const float* __restrict__ W2,
                                                           const float* __restrict__ b2,
                                                           float* __restrict__ img_out){
  __shared__ __align__(1024) unsigned char sA[2][16384];
  __shared__ __align__(1024) unsigned char sW[2][8192];
  int tile = blockIdx.x;
  int b = tile / 25, pbase = (tile % 25) * 64;
  int tid = threadIdx.x, w = tid >> 5, lane = tid & 31;
  int gid = lane >> 2, tig = lane & 3, r7 = lane & 7;

  uint32_t sa0 = (uint32_t)__cvta_generic_to_shared(&sA[0][0]);
  uint32_t sw0 = (uint32_t)__cvta_generic_to_shared(&sW[0][0]);

  {
    const float* Abase = g_attn + (size_t)(tile*64)*DM;
    #pragma unroll
    for (int it=0; it<8; it++){
      int idx = tid + it*256;
      int r = idx >> 5, kc4 = idx & 31;
      int kc = kc4 >> 1, half = kc4 & 1;
      float4 v = *(const float4*)(Abase + r*DM + kc4*4);
      uint32_t h0, l0, h1, l1;
      split2(v.x, v.y, h0, l0);
      split2(v.z, v.w, h1, l1);
      uint32_t addr = sa0 + (uint32_t)(r*256 + ((kc ^ (r & 7)))*16 + half*8);
      sts64(addr,         h0, h1);
      sts64(addr + 16384, l0, l1);
    }
  }

  float oa[16][4];
  #pragma unroll
  for (int i=0;i<16;i++){ oa[i][0]=0.f; oa[i][1]=0.f; oa[i][2]=0.f; oa[i][3]=0.f; }

  int arow = (w & 3)*16 + r7 + ((lane >> 3) & 1)*8;
  int klocal = r7 + ((lane >> 3) & 1)*8;
  int ncsel  = (lane >> 4) & 1;
  int nbase  = (w >> 2) * 16;

  for (int ks=0; ks<8; ks++){
    float4 wreg[4];
    #pragma unroll
    for (int it=0; it<4; it++){
      int idx = tid + it*256;
      int kk = idx >> 6, nc4 = idx & 63;
      wreg[it] = *(const float4*)(W2 + (ks*16 + kk)*CI + nc4*4);
    }
    __syncthreads();
    #pragma unroll
    for (int it=0; it<4; it++){
      int idx = tid + it*256;
      int kk = idx >> 6, nc4 = idx & 63;
      int nc = nc4 >> 1, half = nc4 & 1;
      uint32_t h0, l0, h1, l1;
      split2(wreg[it].x, wreg[it].y, h0, l0);
      split2(wreg[it].z, wreg[it].w, h1, l1);
      uint32_t addr = sw0 + (uint32_t)(kk*512 + (nc ^ (kk & 7))*16 + half*8);
      sts64(addr,        h0, h1);
      sts64(addr + 8192, l0, l1);
    }
    __syncthreads();

    uint32_t ah[4], al[4];
    {
      int kcv = 2*ks + ((lane >> 4) & 1);
      uint32_t aaddr = sa0 + (uint32_t)(arow*256 + ((kcv ^ r7))*16);
      ldsm4(aaddr, ah);
      ldsm4(aaddr + 16384, al);
    }

    #pragma unroll
    for (int p=0; p<8; p++){
      int nc0 = nbase + 2*p;
      uint32_t waddr = sw0 + (uint32_t)(klocal*512 + (((nc0 + ncsel) ^ r7))*16);
      uint32_t wh[4], wl[4];
      ldsm4t(waddr, wh);
      ldsm4t(waddr + 8192, wl);
      mma_bf16(oa[2*p],   ah, wh[0], wh[1]);
      mma_bf16(oa[2*p],   ah, wl[0], wl[1]);
      mma_bf16(oa[2*p],   al, wh[0], wh[1]);
      mma_bf16(oa[2*p+1], ah, wh[2], wh[3]);
      mma_bf16(oa[2*p+1], ah, wl[2], wl[3]);
      mma_bf16(oa[2*p+1], al, wh[2], wh[3]);
    }
  }

  int p0 = pbase + (w & 3)*16 + gid;
  float* outB = img_out + (size_t)b*CI*HW;
  #pragma unroll
  for (int nc=0; nc<16; nc++){
    int c0 = (w >> 2)*128 + nc*8 + 2*tig;
    float bb0 = __ldg(b2 + c0), bb1 = __ldg(b2 + c0 + 1);
    float v00 = oa[nc][0] + bb0, v01 = oa[nc][1] + bb1;
    float v10 = oa[nc][2] + bb0, v11 = oa[nc][3] + bb1;
    outB[(size_t)c0*HW + p0]           = v00;
    outB[(size_t)(c0+1)*HW + p0]       = v01;
    outB[(size_t)c0*HW + p0 + 8]       = v10;
    outB[(size_t)(c0+1)*HW + p0 + 8]   = v11;
    float e00 = fmaxf(v00, 1e-6f), e01 = fmaxf(v01, 1e-6f);
    float e10 = fmaxf(v10, 1e-6f), e11 = fmaxf(v11, 1e-6f);
    float pc0 = e00*e00*e00 + e10*e10*e10;
    float pc1 = e01*e01*e01 + e11*e11*e11;
    pc0 += __shfl_xor_sync(0xffffffffu, pc0, 4);
    pc1 += __shfl_xor_sync(0xffffffffu, pc1, 4);
    pc0 += __shfl_xor_sync(0xffffffffu, pc0, 8);
    pc1 += __shfl_xor_sync(0xffffffffu, pc1, 8);
    pc0 += __shfl_xor_sync(0xffffffffu, pc0, 16);
    pc1 += __shfl_xor_sync(0xffffffffu, pc1, 16);
    if (lane < 4){
      atomicAdd(&g_imgacc[b*CI + c0],     pc0);
      atomicAdd(&g_imgacc[b*CI + c0 + 1], pc1);
    }
  }
}

// ---------------- K7: cloud l2norm + segmented clamp^3 sum -------------------
__global__ __launch_bounds__(256) void cloud_kernel(const float* __restrict__ cf,
                                                    const int* __restrict__ bids,
                                                    float* __restrict__ cloud_out){
  __shared__ float sseg[NB*DM];
  __shared__ float scnt[NB];
  int tid = threadIdx.x;
  for (int i=tid; i<NB*DM; i+=256) sseg[i] = 0.f;
  if (tid < NB) scnt[tid] = 0.f;
  __syncthreads();
  int w = tid >> 5, lane = tid & 31;
  int rbase = blockIdx.x*64 + w*8;
  #pragma unroll
  for (int i=0;i<8;i++){
    int row = rbase + i;
    int bid = bids[row];
    float4 v = *(const float4*)(cf + row*DM + lane*4);
    float sq = v.x*v.x + v.y*v.y + v.z*v.z + v.w*v.w;
    #pragma unroll
    for (int off=16; off; off>>=1) sq += __shfl_xor_sync(0xffffffffu, sq, off);
    float inv = 1.0f / fmaxf(sqrtf(sq), 1e-12f);
    float x0=v.x*inv, x1=v.y*inv, x2=v.z*inv, x3=v.w*inv;
    *(float4*)(cloud_out + row*DM + lane*4) = make_float4(x0,x1,x2,x3);
    float c0=fmaxf(x0,1e-6f), c1=fmaxf(x1,1e-6f), c2=fmaxf(x2,1e-6f), c3=fmaxf(x3,1e-6f);
    float* sp = sseg + bid*DM + lane*4;
    atomicAdd(sp+0, c0*c0*c0);
    atomicAdd(sp+1, c1*c1*c1);
    atomicAdd(sp+2, c2*c2*c2);
    atomicAdd(sp+3, c3*c3*c3);
    if (lane == 0) atomicAdd(&scnt[bid], 1.0f);
  }
  __syncthreads();
  for (int i=tid; i<NB*DM; i+=256) atomicAdd(&g_seg[i], sseg[i]);
  if (tid < NB) atomicAdd(&g_cnt[tid], scnt[tid]);
}

// ---------------- K8: finalize GeM outputs ----------------
__global__ void finalize_kernel(float* __restrict__ image_gem, float* __restrict__ cloud_gem){
  int i = blockIdx.x*256 + threadIdx.x;
  if (i < NB*CI) image_gem[i] = cbrtf(g_imgacc[i] * (1.0f/1600.0f));
  if (i < NB*DM) cloud_gem[i] = cbrtf(g_seg[i] / fmaxf(g_cnt[i>>7], 1.0f));
}

// ---------------- launch ----------------
extern "C" void kernel_launch(void* const* d_in, const int* in_sizes, int n_in,
                              void* d_out, int out_size){
  const float* img  = (const float*)d_in[0];
  const float* cf   = (const float*)d_in[1];
  const int*   bids = (const int*)  d_in[2];
  const float* W1   = (const float*)d_in[3];
  const float* b1   = (const float*)d_in[4];
  const float* W2   = (const float*)d_in[5];
  const float* b2   = (const float*)d_in[6];

  float* out       = (float*)d_out;
  float* img_out   = out;                                  // 8*256*1600
  float* cloud_out = out + (size_t)NB*CI*HW;               // 32768*128
  float* image_gem = cloud_out + (size_t)NCLOUD*DM;        // 2048
  float* cloud_gem = image_gem + NB*CI;                    // 1024

  zero_kernel<<<8, 256>>>();
  gemm1_mma_kernel<<<200, 256>>>(img, W1, b1);
  attn_bf16_kernel<<<dim3(13, NHEAD, NB), 256>>>();
  gemm2_mma_kernel<<<200, 256>>>(W2, b2, img_out);
  cloud_kernel<<<512, 256>>>(cf, bids, cloud_out);
  finalize_kernel<<<8, 256>>>(image_gem, cloud_gem);
}